// round 1
// baseline (speedup 1.0000x reference)
#include <cuda_runtime.h>

// ---------------------------------------------------------------------------
// DeBiLevelRoutingAttention block, fp32 baseline.
// x:(16,512,56,56)  w_qkv:(1536,512)  b_qkv:(1536)  w_lepe:(512,1,3,3) b_lepe:(512)
// out:(16,512,56,56)
// ---------------------------------------------------------------------------

#define N_IMG  16
#define C_DIM  512
#define H_IMG  56
#define W_IMG  56
#define HW     3136
#define QKC    512          // QK channels
#define OCH    1536         // 2*QK + DIM
#define NWIN   7
#define P2     49
#define W2     64
#define TOPK   4
#define HEADS  8
#define HD     64
#define SCALE  0.04419417382415922f   // 512^-0.5

// ----------------------------- scratch (device globals, allocation-free) ----
__device__ float g_q [(size_t)N_IMG * P2 * W2 * C_DIM];         //  98 MB, [n][p][pix][c]
__device__ float g_kv[(size_t)N_IMG * P2 * W2 * 1024];          // 196 MB, [n][p][pix][c] c<512:k, c>=512:v
__device__ float g_ao[(size_t)N_IMG * P2 * W2 * C_DIM];         //  98 MB, attention out
__device__ float g_qwin[(size_t)N_IMG * P2 * C_DIM];
__device__ float g_kwin[(size_t)N_IMG * P2 * C_DIM];
__device__ int   g_idx [N_IMG * P2 * TOPK];

// ===========================================================================
// Kernel 1: QKV GEMM (M=50176 pixels, N=1536, K=512) fused with bias add and
// window-partition scatter. grid (392, 12), block 256, 128x128x8 tiles, 8x8/thr.
// ===========================================================================
__global__ __launch_bounds__(256) void k1_qkv(const float* __restrict__ x,
                                              const float* __restrict__ w,
                                              const float* __restrict__ bqkv) {
    __shared__ float As[8][128];
    __shared__ float Bs[8][128];
    const int t  = threadIdx.x;
    const int m0 = blockIdx.x * 128;
    const int o0 = blockIdx.y * 128;

    // A loader: 8 k-rows x 128 pixels, float4 per thread
    const int la_k = t >> 5;
    const int la_m = (t & 31) << 2;
    const int mA   = m0 + la_m;
    const int nA   = mA / HW;
    const int hwA  = mA - nA * HW;
    const float* aptr = x + (size_t)nA * C_DIM * HW + hwA;

    // B loader: w_qkv[o][k] (k contiguous) -> Bs[k][o]
    const int lb_o = t >> 1;
    const int lb_k = (t & 1) << 2;
    const float* bptr = w + (size_t)(o0 + lb_o) * C_DIM + lb_k;

    const int ty = t >> 4;   // 0..15 -> pixel sub-row
    const int tx = t & 15;   // 0..15 -> out-channel sub-col

    float acc[8][8];
#pragma unroll
    for (int i = 0; i < 8; i++)
#pragma unroll
        for (int j = 0; j < 8; j++) acc[i][j] = 0.f;

    float4 av = *(const float4*)(aptr + (size_t)la_k * HW);
    float4 bv = *(const float4*)(bptr);

    for (int k0 = 0; k0 < C_DIM; k0 += 8) {
        *(float4*)&As[la_k][la_m] = av;
        Bs[lb_k + 0][lb_o] = bv.x;
        Bs[lb_k + 1][lb_o] = bv.y;
        Bs[lb_k + 2][lb_o] = bv.z;
        Bs[lb_k + 3][lb_o] = bv.w;
        __syncthreads();
        if (k0 + 8 < C_DIM) {  // prefetch next tiles while computing
            av = *(const float4*)(aptr + (size_t)(k0 + 8 + la_k) * HW);
            bv = *(const float4*)(bptr + k0 + 8);
        }
#pragma unroll
        for (int kk = 0; kk < 8; kk++) {
            float4 a0 = *(float4*)&As[kk][ty * 8];
            float4 a1 = *(float4*)&As[kk][ty * 8 + 4];
            float4 b0 = *(float4*)&Bs[kk][tx * 8];
            float4 b1 = *(float4*)&Bs[kk][tx * 8 + 4];
            float ar[8] = {a0.x, a0.y, a0.z, a0.w, a1.x, a1.y, a1.z, a1.w};
            float br[8] = {b0.x, b0.y, b0.z, b0.w, b1.x, b1.y, b1.z, b1.w};
#pragma unroll
            for (int i = 0; i < 8; i++)
#pragma unroll
                for (int j = 0; j < 8; j++) acc[i][j] += ar[i] * br[j];
        }
        __syncthreads();
    }

    const int obase = o0 + tx * 8;
    float bias[8];
#pragma unroll
    for (int j = 0; j < 8; j++) bias[j] = bqkv[obase + j];

#pragma unroll
    for (int i = 0; i < 8; i++) {
        int m  = m0 + ty * 8 + i;
        int n  = m / HW;
        int hw = m - n * HW;
        int h  = hw / W_IMG;
        int wp = hw - h * W_IMG;
        int p  = (h >> 3) * NWIN + (wp >> 3);
        int pix = ((h & 7) << 3) + (wp & 7);
        size_t base = (size_t)((n * P2 + p) * W2 + pix);
        float* dst = (obase < QKC)
                   ? (g_q  + base * C_DIM + obase)
                   : (g_kv + base * 1024  + (obase - QKC));
        float4 s0 = make_float4(acc[i][0] + bias[0], acc[i][1] + bias[1],
                                acc[i][2] + bias[2], acc[i][3] + bias[3]);
        float4 s1 = make_float4(acc[i][4] + bias[4], acc[i][5] + bias[5],
                                acc[i][6] + bias[6], acc[i][7] + bias[7]);
        *(float4*)dst       = s0;
        *(float4*)(dst + 4) = s1;
    }
}

// ===========================================================================
// Kernel 2: per-window means of q and k. grid 784, block 256.
// ===========================================================================
__global__ __launch_bounds__(256) void k2_mean() {
    const int np = blockIdx.x;                 // n*49+p
    const float* qb = g_q  + (size_t)np * W2 * C_DIM;
    const float* kb = g_kv + (size_t)np * W2 * 1024;
    for (int c = threadIdx.x; c < C_DIM; c += 256) {
        float sq = 0.f, sk = 0.f;
#pragma unroll 8
        for (int pix = 0; pix < W2; pix++) {
            sq += qb[(size_t)pix * C_DIM + c];
            sk += kb[(size_t)pix * 1024  + c];
        }
        g_qwin[(size_t)np * C_DIM + c] = sq * (1.f / 64.f);
        g_kwin[(size_t)np * C_DIM + c] = sk * (1.f / 64.f);
    }
}

// ===========================================================================
// Kernel 3: routing logits (49x49 per image) + top-4 set. grid 784, block 64.
// Order of the top-4 does not matter (joint softmax over the union of keys).
// ===========================================================================
__global__ __launch_bounds__(64) void k3_route() {
    __shared__ float qs[512];
    __shared__ float lg[P2];
    const int np = blockIdx.x;
    const int n  = np / P2;
    const int t  = threadIdx.x;
    for (int c = t; c < 512; c += 64)
        qs[c] = g_qwin[(size_t)np * 512 + c] * SCALE;
    __syncthreads();
    if (t < P2) {
        const float4* kr = (const float4*)(g_kwin + (size_t)(n * P2 + t) * 512);
        float s = 0.f;
#pragma unroll 4
        for (int c4 = 0; c4 < 128; c4++) {
            float4 k4 = kr[c4];
            s += qs[c4 * 4 + 0] * k4.x + qs[c4 * 4 + 1] * k4.y +
                 qs[c4 * 4 + 2] * k4.z + qs[c4 * 4 + 3] * k4.w;
        }
        lg[t] = s;
    }
    __syncthreads();
    if (t == 0) {
        unsigned long long used = 0;
        for (int sel = 0; sel < TOPK; sel++) {
            float best = -1e30f; int bi = 0;
            for (int m = 0; m < P2; m++) {
                if ((used >> m) & 1ULL) continue;
                if (lg[m] > best) { best = lg[m]; bi = m; }
            }
            used |= 1ULL << bi;
            g_idx[np * TOPK + sel] = bi;
        }
    }
}

// ===========================================================================
// Kernel 4: windowed attention, one block per (head, n*p). block 256 =
// 64 q-rows x 4 lanes; each lane owns 16 of 64 head dims. Online softmax
// over 4 selected windows (64 keys each). smem 32KB (K + V tile).
// ===========================================================================
__global__ __launch_bounds__(256, 1) void k4_attn() {
    __shared__ float Kc[64][64];
    __shared__ float Vc[64][64];
    const int head = blockIdx.x;
    const int np   = blockIdx.y;
    const int n    = np / P2;
    const int t    = threadIdx.x;
    const int r    = t >> 2;   // q row 0..63
    const int g    = t & 3;    // dim-quarter 0..3

    const float* qrow = g_q + ((size_t)np * W2 + r) * C_DIM + head * HD + g * 16;
    float qf[16];
#pragma unroll
    for (int d = 0; d < 16; d++) qf[d] = qrow[d] * SCALE;

    float O[16];
#pragma unroll
    for (int d = 0; d < 16; d++) O[d] = 0.f;
    float mrun = -1e30f, lrun = 0.f;

    for (int tsel = 0; tsel < TOPK; tsel++) {
        const int widx = g_idx[np * TOPK + tsel];
        const size_t kvbase = (size_t)(n * P2 + widx) * W2 * 1024 + head * HD;
#pragma unroll
        for (int i = 0; i < 4; i++) {
            int f4  = i * 256 + t;         // 0..1023 float4 slots
            int pix = f4 >> 4;
            int dq  = (f4 & 15) << 2;
            *(float4*)&Kc[pix][dq] = *(const float4*)(g_kv + kvbase + (size_t)pix * 1024 + dq);
            *(float4*)&Vc[pix][dq] = *(const float4*)(g_kv + kvbase + (size_t)pix * 1024 + 512 + dq);
        }
        __syncthreads();

        float s[64];
#pragma unroll
        for (int j = 0; j < 64; j++) {
            float a = 0.f;
            const float4* kr = (const float4*)&Kc[j][g * 16];
            float4 k0 = kr[0], k1 = kr[1], k2 = kr[2], k3 = kr[3];
            a += qf[0]*k0.x + qf[1]*k0.y + qf[2]*k0.z + qf[3]*k0.w;
            a += qf[4]*k1.x + qf[5]*k1.y + qf[6]*k1.z + qf[7]*k1.w;
            a += qf[8]*k2.x + qf[9]*k2.y + qf[10]*k2.z + qf[11]*k2.w;
            a += qf[12]*k3.x + qf[13]*k3.y + qf[14]*k3.z + qf[15]*k3.w;
            s[j] = a;
        }
        // reduce partial dots across the 4 lanes of this q-row
#pragma unroll
        for (int j = 0; j < 64; j++) {
            s[j] += __shfl_xor_sync(0xffffffffu, s[j], 1);
            s[j] += __shfl_xor_sync(0xffffffffu, s[j], 2);
        }
        float mc = -1e30f;
#pragma unroll
        for (int j = 0; j < 64; j++) mc = fmaxf(mc, s[j]);
        float mnew = fmaxf(mrun, mc);
        float corr = __expf(mrun - mnew);
        lrun *= corr;
#pragma unroll
        for (int d = 0; d < 16; d++) O[d] *= corr;
        float ls = 0.f;
#pragma unroll
        for (int j = 0; j < 64; j++) {
            float pv = __expf(s[j] - mnew);
            s[j] = pv;
            ls += pv;
        }
        lrun += ls;
        mrun = mnew;
#pragma unroll
        for (int j = 0; j < 64; j++) {
            float pj = s[j];
            const float4* vr = (const float4*)&Vc[j][g * 16];
            float4 v0 = vr[0], v1 = vr[1], v2 = vr[2], v3 = vr[3];
            O[0]  += pj * v0.x;  O[1]  += pj * v0.y;  O[2]  += pj * v0.z;  O[3]  += pj * v0.w;
            O[4]  += pj * v1.x;  O[5]  += pj * v1.y;  O[6]  += pj * v1.z;  O[7]  += pj * v1.w;
            O[8]  += pj * v2.x;  O[9]  += pj * v2.y;  O[10] += pj * v2.z;  O[11] += pj * v2.w;
            O[12] += pj * v3.x;  O[13] += pj * v3.y;  O[14] += pj * v3.z;  O[15] += pj * v3.w;
        }
        __syncthreads();   // before next chunk overwrites Kc/Vc
    }

    const float inv = 1.f / lrun;
    float* dst = g_ao + ((size_t)np * W2 + r) * C_DIM + head * HD + g * 16;
#pragma unroll
    for (int d = 0; d < 16; d++) dst[d] = O[d] * inv;
}

// ===========================================================================
// Kernel 5: LePE depthwise 3x3 on v (read from windowed kv with cross-window
// halo addressing) + attention output, transposed to NCHW via smem.
// grid (16 cblk, 49 p, 16 n), block 256 (32 channels x 8 pixel-rows).
// ===========================================================================
__global__ __launch_bounds__(256) void k5_out(const float* __restrict__ wlepe,
                                              const float* __restrict__ blepe,
                                              float* __restrict__ out) {
    __shared__ float stage[64 * 36];   // [pix][c], stride 36 -> conflict-free transpose
    const int cb = blockIdx.x;         // 16 blocks of 32 channels
    const int p  = blockIdx.y;
    const int n  = blockIdx.z;
    const int c0 = cb * 32;
    const int t  = threadIdx.x;
    const int c  = t & 31;             // channel within block
    const int pr = t >> 5;             // 0..7

    float wl[9];
#pragma unroll
    for (int k = 0; k < 9; k++) wl[k] = wlepe[(c0 + c) * 9 + k];
    const float bias = blepe[c0 + c];

    const int wh0 = (p / NWIN) * 8;
    const int ww0 = (p % NWIN) * 8;

    for (int pg = 0; pg < 8; pg++) {
        int pix = pg * 8 + pr;
        int ih = pix >> 3, iw = pix & 7;
        int h = wh0 + ih, w = ww0 + iw;
        float acc = bias;
#pragma unroll
        for (int kh = 0; kh < 3; kh++) {
            int hh = h + kh - 1;
            if (hh < 0 || hh >= H_IMG) continue;
#pragma unroll
            for (int kw = 0; kw < 3; kw++) {
                int ww = w + kw - 1;
                if (ww < 0 || ww >= W_IMG) continue;
                int pp   = (hh >> 3) * NWIN + (ww >> 3);
                int ppix = ((hh & 7) << 3) + (ww & 7);
                float vv = g_kv[((size_t)(n * P2 + pp) * W2 + ppix) * 1024 + 512 + c0 + c];
                acc += vv * wl[kh * 3 + kw];
            }
        }
        acc += g_ao[((size_t)(n * P2 + p) * W2 + pix) * C_DIM + c0 + c];
        stage[pix * 36 + c] = acc;
    }
    __syncthreads();

    // transposed write: 8 contiguous pixels (32B, aligned) per 8 lanes
    const int wc = t >> 3;   // 0..31 channel
    const int wx = t & 7;    // 0..7  w within window
    const size_t obase = ((size_t)n * C_DIM + c0 + wc) * HW;
    for (int h = 0; h < 8; h++) {
        out[obase + (size_t)(wh0 + h) * W_IMG + ww0 + wx] = stage[(h * 8 + wx) * 36 + wc];
    }
}

// ===========================================================================
extern "C" void kernel_launch(void* const* d_in, const int* in_sizes, int n_in,
                              void* d_out, int out_size) {
    const float* x      = (const float*)d_in[0];
    const float* w_qkv  = (const float*)d_in[1];
    const float* b_qkv  = (const float*)d_in[2];
    const float* w_lepe = (const float*)d_in[3];
    const float* b_lepe = (const float*)d_in[4];
    float* out = (float*)d_out;

    k1_qkv<<<dim3(392, 12), 256>>>(x, w_qkv, b_qkv);
    k2_mean<<<784, 256>>>();
    k3_route<<<784, 64>>>();
    k4_attn<<<dim3(HEADS, N_IMG * P2), 256>>>();
    k5_out<<<dim3(16, P2, N_IMG), 256>>>(w_lepe, b_lepe, out);
}

// round 3
// speedup vs baseline: 1.9043x; 1.9043x over previous
#include <cuda_runtime.h>
#include <cstdint>

// ---------------------------------------------------------------------------
// DeBiLevelRoutingAttention block. Round 3: QKV GEMM via mma.sync TF32
// (tcgen05 unavailable: harness targets compute_100 without the 'a' suffix).
// x:(16,512,56,56)  w_qkv:(1536,512)  b_qkv:(1536)  w_lepe:(512,1,3,3) b_lepe:(512)
// ---------------------------------------------------------------------------

#define N_IMG  16
#define C_DIM  512
#define H_IMG  56
#define W_IMG  56
#define HW     3136
#define QKC    512
#define NWIN   7
#define P2     49
#define W2     64
#define TOPK   4
#define HEADS  8
#define HD     64
#define SCALE  0.04419417382415922f   // 512^-0.5

// ----------------------------- scratch ------------------------------------
__device__ float g_q [(size_t)N_IMG * P2 * W2 * C_DIM];
__device__ float g_kv[(size_t)N_IMG * P2 * W2 * 1024];
__device__ float g_ao[(size_t)N_IMG * P2 * W2 * C_DIM];
__device__ float g_qwin[(size_t)N_IMG * P2 * C_DIM];
__device__ float g_kwin[(size_t)N_IMG * P2 * C_DIM];
__device__ int   g_idx [N_IMG * P2 * TOPK];

// ----------------------------- helpers ------------------------------------
__device__ __forceinline__ uint32_t f2tf32(float f) {
    uint32_t r;
    asm("cvt.rna.tf32.f32 %0, %1;" : "=r"(r) : "f"(f));
    return r;
}
__device__ __forceinline__ void mma_tf32(float c[4], const uint32_t a[4],
                                         uint32_t b0, uint32_t b1) {
    asm volatile(
        "mma.sync.aligned.m16n8k8.row.col.f32.tf32.tf32.f32 "
        "{%0,%1,%2,%3}, {%4,%5,%6,%7}, {%8,%9}, {%0,%1,%2,%3};"
        : "+f"(c[0]), "+f"(c[1]), "+f"(c[2]), "+f"(c[3])
        : "r"(a[0]), "r"(a[1]), "r"(a[2]), "r"(a[3]), "r"(b0), "r"(b1));
}

// ===========================================================================
// Kernel 1: QKV GEMM, TF32 mma.sync.  C[50176][1536] = A[M][512] @ B[1536][512]^T
// Block tile 128x128, K-chunk 32, double-buffered smem + register prefetch.
// grid (12 n-blocks, 392 m-blocks) so concurrent blocks share the A tile in L2.
// 8 warps = 4(M) x 2(N); warp tile 32x64; fused bias + window scatter epilogue.
// ===========================================================================
#define K1_PITCH 136                       // 32-row k-major tiles, +8 pad: conflict-free
#define K1_STG   (32 * K1_PITCH)           // floats per stage
#define K1_SMEMB (4 * K1_STG * 4)          // bytes: A x2 + B x2

__global__ __launch_bounds__(256) void k1_qkv_mma(const float* __restrict__ x,
                                                  const float* __restrict__ w,
                                                  const float* __restrict__ bqkv) {
    extern __shared__ float sm[];
    float* As = sm;                        // [2][32][136]
    float* Bs = sm + 2 * K1_STG;           // [2][32][136]

    const int t  = threadIdx.x;
    const int o0 = blockIdx.x * 128;
    const int m0 = blockIdx.y * 128;

    // A loader: k-row = t>>3, four float4 along m at (t&7)*4 + i*32
    const int akr = t >> 3;
    const int am4 = (t & 7) * 4;
    // B loader: o-row = t>>1, four float4 along k at (t&1)*16 + i*4
    const int bor = t >> 1;
    const int bk  = (t & 1) * 16;

    const int wid = t >> 5, lane = t & 31;
    const int mw = (wid & 3) * 32;
    const int nw = (wid >> 2) * 64;
    const int lq = lane & 3;               // k / col-pair selector
    const int lr = lane >> 2;              // row-in-8 selector

    float c[2][8][4];
#pragma unroll
    for (int mt = 0; mt < 2; mt++)
#pragma unroll
        for (int nt = 0; nt < 8; nt++)
#pragma unroll
            for (int i = 0; i < 4; i++) c[mt][nt][i] = 0.f;

    float4 aR[4], bR[4];
    // ---- prefetch chunk 0 ----
#pragma unroll
    for (int i = 0; i < 4; i++) {
        int m = m0 + am4 + i * 32;
        int n = m / HW, hw = m - n * HW;
        aR[i] = *(const float4*)(x + (size_t)n * (C_DIM * HW) + (size_t)akr * HW + hw);
        bR[i] = *(const float4*)(w + (size_t)(o0 + bor) * C_DIM + bk + i * 4);
    }

    for (int kc = 0; kc < 16; kc++) {
        const int st = kc & 1;
        float* A = As + st * K1_STG;
        float* B = Bs + st * K1_STG;
        // store current chunk (tf32-rounded)
#pragma unroll
        for (int i = 0; i < 4; i++) {
            uint32_t* d = (uint32_t*)&A[akr * K1_PITCH + am4 + i * 32];
            uint32_t r0 = f2tf32(aR[i].x), r1 = f2tf32(aR[i].y);
            uint32_t r2 = f2tf32(aR[i].z), r3 = f2tf32(aR[i].w);
            asm volatile("st.shared.v4.b32 [%0], {%1,%2,%3,%4};"
                         :: "l"(d), "r"(r0), "r"(r1), "r"(r2), "r"(r3) : "memory");
            uint32_t* bd = (uint32_t*)B;
            bd[(bk + i * 4 + 0) * K1_PITCH + bor] = f2tf32(bR[i].x);
            bd[(bk + i * 4 + 1) * K1_PITCH + bor] = f2tf32(bR[i].y);
            bd[(bk + i * 4 + 2) * K1_PITCH + bor] = f2tf32(bR[i].z);
            bd[(bk + i * 4 + 3) * K1_PITCH + bor] = f2tf32(bR[i].w);
        }
        __syncthreads();
        if (kc < 15) {  // prefetch next chunk while computing
            const int k0 = (kc + 1) * 32;
#pragma unroll
            for (int i = 0; i < 4; i++) {
                int m = m0 + am4 + i * 32;
                int n = m / HW, hw = m - n * HW;
                aR[i] = *(const float4*)(x + (size_t)n * (C_DIM * HW) + (size_t)(k0 + akr) * HW + hw);
                bR[i] = *(const float4*)(w + (size_t)(o0 + bor) * C_DIM + k0 + bk + i * 4);
            }
        }
        const uint32_t* Au = (const uint32_t*)A;
        const uint32_t* Bu = (const uint32_t*)B;
#pragma unroll
        for (int ks = 0; ks < 4; ks++) {
            const int kk = ks * 8;
            uint32_t a[2][4];
#pragma unroll
            for (int mt = 0; mt < 2; mt++) {
                const int mb = mw + mt * 16 + lr;
                a[mt][0] = Au[(kk + lq)     * K1_PITCH + mb];
                a[mt][1] = Au[(kk + lq)     * K1_PITCH + mb + 8];
                a[mt][2] = Au[(kk + 4 + lq) * K1_PITCH + mb];
                a[mt][3] = Au[(kk + 4 + lq) * K1_PITCH + mb + 8];
            }
#pragma unroll
            for (int nt = 0; nt < 8; nt++) {
                const int nb = nw + nt * 8 + lr;
                uint32_t b0 = Bu[(kk + lq)     * K1_PITCH + nb];
                uint32_t b1 = Bu[(kk + 4 + lq) * K1_PITCH + nb];
                mma_tf32(c[0][nt], a[0], b0, b1);
                mma_tf32(c[1][nt], a[1], b0, b1);
            }
        }
        __syncthreads();
    }

    // ----- epilogue: bias + window scatter -----
    const bool isq = (o0 < QKC);           // whole 128-col block is q or kv
#pragma unroll
    for (int mt = 0; mt < 2; mt++) {
#pragma unroll
        for (int half = 0; half < 2; half++) {
            const int row = mw + mt * 16 + lr + half * 8;
            const int m   = m0 + row;
            const int n   = m / HW;
            const int hw  = m - n * HW;
            const int h   = hw / W_IMG;
            const int wp  = hw - h * W_IMG;
            const int p   = (h >> 3) * NWIN + (wp >> 3);
            const int pix = ((h & 7) << 3) + (wp & 7);
            const size_t base = (size_t)((n * P2 + p) * W2 + pix);
            float* dst = isq ? (g_q + base * C_DIM + o0)
                             : (g_kv + base * 1024 + (o0 - QKC));
#pragma unroll
            for (int nt = 0; nt < 8; nt++) {
                const int col = nw + nt * 8 + lq * 2;
                float2 v;
                v.x = c[mt][nt][half * 2 + 0] + bqkv[o0 + col];
                v.y = c[mt][nt][half * 2 + 1] + bqkv[o0 + col + 1];
                *(float2*)(dst + col) = v;
            }
        }
    }
}

// ===========================================================================
// Kernel 2: per-window means of q and k. grid 784, block 256.
// ===========================================================================
__global__ __launch_bounds__(256) void k2_mean() {
    const int np = blockIdx.x;
    const float* qb = g_q  + (size_t)np * W2 * C_DIM;
    const float* kb = g_kv + (size_t)np * W2 * 1024;
    for (int c = threadIdx.x; c < C_DIM; c += 256) {
        float sq = 0.f, sk = 0.f;
#pragma unroll 8
        for (int pix = 0; pix < W2; pix++) {
            sq += qb[(size_t)pix * C_DIM + c];
            sk += kb[(size_t)pix * 1024  + c];
        }
        g_qwin[(size_t)np * C_DIM + c] = sq * (1.f / 64.f);
        g_kwin[(size_t)np * C_DIM + c] = sk * (1.f / 64.f);
    }
}

// ===========================================================================
// Kernel 3: routing logits + top-4 set. grid 784, block 64.
// ===========================================================================
__global__ __launch_bounds__(64) void k3_route() {
    __shared__ float qs[512];
    __shared__ float lg[P2];
    const int np = blockIdx.x;
    const int n  = np / P2;
    const int t  = threadIdx.x;
    for (int c = t; c < 512; c += 64)
        qs[c] = g_qwin[(size_t)np * 512 + c] * SCALE;
    __syncthreads();
    if (t < P2) {
        const float4* kr = (const float4*)(g_kwin + (size_t)(n * P2 + t) * 512);
        float s = 0.f;
#pragma unroll 4
        for (int c4 = 0; c4 < 128; c4++) {
            float4 k4 = kr[c4];
            s += qs[c4 * 4 + 0] * k4.x + qs[c4 * 4 + 1] * k4.y +
                 qs[c4 * 4 + 2] * k4.z + qs[c4 * 4 + 3] * k4.w;
        }
        lg[t] = s;
    }
    __syncthreads();
    if (t == 0) {
        unsigned long long used = 0;
        for (int sel = 0; sel < TOPK; sel++) {
            float best = -1e30f; int bi = 0;
            for (int m = 0; m < P2; m++) {
                if ((used >> m) & 1ULL) continue;
                if (lg[m] > best) { best = lg[m]; bi = m; }
            }
            used |= 1ULL << bi;
            g_idx[np * TOPK + sel] = bi;
        }
    }
}

// ===========================================================================
// Kernel 4: windowed attention. 128 threads per (head, np): each thread owns
// 2 q-rows x 16 dims (K/V smem reads amortized over 2 rows -> LDS halved).
// Keys in chunks of 32 with online softmax. smem 32KB.
// ===========================================================================
__global__ __launch_bounds__(128) void k4_attn() {
    __shared__ float Kc[64][64];
    __shared__ float Vc[64][64];
    const int head = blockIdx.x;
    const int np   = blockIdx.y;
    const int n    = np / P2;
    const int t    = threadIdx.x;
    const int g    = t & 3;                // 16-dim quarter
    const int rs   = t >> 2;               // 0..31 -> rows rs, rs+32

    float qf[2][16], O[2][16];
#pragma unroll
    for (int rr = 0; rr < 2; rr++) {
        const float* qrow = g_q + ((size_t)np * W2 + rs + rr * 32) * C_DIM + head * HD + g * 16;
#pragma unroll
        for (int d = 0; d < 16; d++) { qf[rr][d] = qrow[d] * SCALE; O[rr][d] = 0.f; }
    }
    float mrun[2] = {-1e30f, -1e30f}, lrun[2] = {0.f, 0.f};

    for (int tsel = 0; tsel < TOPK; tsel++) {
        const int widx = g_idx[np * TOPK + tsel];
        const size_t kvbase = (size_t)(n * P2 + widx) * W2 * 1024 + head * HD;
#pragma unroll
        for (int i = 0; i < 8; i++) {
            int f4  = i * 128 + t;          // 1024 float4 slots each for K and V
            int pix = f4 >> 4;
            int dq  = (f4 & 15) << 2;
            *(float4*)&Kc[pix][dq] = *(const float4*)(g_kv + kvbase + (size_t)pix * 1024 + dq);
            *(float4*)&Vc[pix][dq] = *(const float4*)(g_kv + kvbase + (size_t)pix * 1024 + 512 + dq);
        }
        __syncthreads();

#pragma unroll
        for (int ch = 0; ch < 2; ch++) {
            float s[2][32];
#pragma unroll
            for (int j = 0; j < 32; j++) {
                const int jj = ch * 32 + j;
                const float4* kr = (const float4*)&Kc[jj][g * 16];
                float4 k0 = kr[0], k1 = kr[1], k2 = kr[2], k3 = kr[3];
#pragma unroll
                for (int rr = 0; rr < 2; rr++) {
                    const float* q = qf[rr];
                    float a = q[0]*k0.x + q[1]*k0.y + q[2]*k0.z + q[3]*k0.w
                            + q[4]*k1.x + q[5]*k1.y + q[6]*k1.z + q[7]*k1.w
                            + q[8]*k2.x + q[9]*k2.y + q[10]*k2.z + q[11]*k2.w
                            + q[12]*k3.x + q[13]*k3.y + q[14]*k3.z + q[15]*k3.w;
                    s[rr][j] = a;
                }
            }
#pragma unroll
            for (int rr = 0; rr < 2; rr++)
#pragma unroll
                for (int j = 0; j < 32; j++) {
                    s[rr][j] += __shfl_xor_sync(0xffffffffu, s[rr][j], 1);
                    s[rr][j] += __shfl_xor_sync(0xffffffffu, s[rr][j], 2);
                }
#pragma unroll
            for (int rr = 0; rr < 2; rr++) {
                float mc = -1e30f;
#pragma unroll
                for (int j = 0; j < 32; j++) mc = fmaxf(mc, s[rr][j]);
                float mnew = fmaxf(mrun[rr], mc);
                float corr = __expf(mrun[rr] - mnew);
                lrun[rr] *= corr;
#pragma unroll
                for (int d = 0; d < 16; d++) O[rr][d] *= corr;
                float ls = 0.f;
#pragma unroll
                for (int j = 0; j < 32; j++) {
                    float pv = __expf(s[rr][j] - mnew);
                    s[rr][j] = pv;
                    ls += pv;
                }
                lrun[rr] += ls;
                mrun[rr] = mnew;
            }
#pragma unroll
            for (int j = 0; j < 32; j++) {
                const int jj = ch * 32 + j;
                const float4* vr = (const float4*)&Vc[jj][g * 16];
                float4 v0 = vr[0], v1 = vr[1], v2 = vr[2], v3 = vr[3];
#pragma unroll
                for (int rr = 0; rr < 2; rr++) {
                    const float pj = s[rr][j];
                    float* o = O[rr];
                    o[0]  += pj * v0.x;  o[1]  += pj * v0.y;  o[2]  += pj * v0.z;  o[3]  += pj * v0.w;
                    o[4]  += pj * v1.x;  o[5]  += pj * v1.y;  o[6]  += pj * v1.z;  o[7]  += pj * v1.w;
                    o[8]  += pj * v2.x;  o[9]  += pj * v2.y;  o[10] += pj * v2.z;  o[11] += pj * v2.w;
                    o[12] += pj * v3.x;  o[13] += pj * v3.y;  o[14] += pj * v3.z;  o[15] += pj * v3.w;
                }
            }
        }
        __syncthreads();
    }

#pragma unroll
    for (int rr = 0; rr < 2; rr++) {
        const float inv = 1.f / lrun[rr];
        float* dst = g_ao + ((size_t)np * W2 + rs + rr * 32) * C_DIM + head * HD + g * 16;
#pragma unroll
        for (int d = 0; d < 16; d += 4) {
            float4 v = make_float4(O[rr][d] * inv, O[rr][d + 1] * inv,
                                   O[rr][d + 2] * inv, O[rr][d + 3] * inv);
            *(float4*)(dst + d) = v;
        }
    }
}

// ===========================================================================
// Kernel 5: LePE depthwise 3x3 + attn out, NCHW transpose.
// ===========================================================================
__global__ __launch_bounds__(256) void k5_out(const float* __restrict__ wlepe,
                                              const float* __restrict__ blepe,
                                              float* __restrict__ out) {
    __shared__ float stage[64 * 36];
    const int cb = blockIdx.x;
    const int p  = blockIdx.y;
    const int n  = blockIdx.z;
    const int c0 = cb * 32;
    const int t  = threadIdx.x;
    const int c  = t & 31;
    const int pr = t >> 5;

    float wl[9];
#pragma unroll
    for (int k = 0; k < 9; k++) wl[k] = wlepe[(c0 + c) * 9 + k];
    const float bias = blepe[c0 + c];

    const int wh0 = (p / NWIN) * 8;
    const int ww0 = (p % NWIN) * 8;

    for (int pg = 0; pg < 8; pg++) {
        int pix = pg * 8 + pr;
        int ih = pix >> 3, iw = pix & 7;
        int h = wh0 + ih, w = ww0 + iw;
        float acc = bias;
#pragma unroll
        for (int kh = 0; kh < 3; kh++) {
            int hh = h + kh - 1;
            if (hh < 0 || hh >= H_IMG) continue;
#pragma unroll
            for (int kw = 0; kw < 3; kw++) {
                int ww = w + kw - 1;
                if (ww < 0 || ww >= W_IMG) continue;
                int pp   = (hh >> 3) * NWIN + (ww >> 3);
                int ppix = ((hh & 7) << 3) + (ww & 7);
                float vv = g_kv[((size_t)(n * P2 + pp) * W2 + ppix) * 1024 + 512 + c0 + c];
                acc += vv * wl[kh * 3 + kw];
            }
        }
        acc += g_ao[((size_t)(n * P2 + p) * W2 + pix) * C_DIM + c0 + c];
        stage[pix * 36 + c] = acc;
    }
    __syncthreads();

    const int wc = t >> 3;
    const int wx = t & 7;
    const size_t obase = ((size_t)n * C_DIM + c0 + wc) * HW;
    for (int h = 0; h < 8; h++) {
        out[obase + (size_t)(wh0 + h) * W_IMG + ww0 + wx] = stage[(h * 8 + wx) * 36 + wc];
    }
}

// ===========================================================================
extern "C" void kernel_launch(void* const* d_in, const int* in_sizes, int n_in,
                              void* d_out, int out_size) {
    const float* x      = (const float*)d_in[0];
    const float* w_qkv  = (const float*)d_in[1];
    const float* b_qkv  = (const float*)d_in[2];
    const float* w_lepe = (const float*)d_in[3];
    const float* b_lepe = (const float*)d_in[4];
    float* out = (float*)d_out;

    cudaFuncSetAttribute(k1_qkv_mma, cudaFuncAttributeMaxDynamicSharedMemorySize, K1_SMEMB);

    k1_qkv_mma<<<dim3(12, 392), 256, K1_SMEMB>>>(x, w_qkv, b_qkv);
    k2_mean<<<784, 256>>>();
    k3_route<<<784, 64>>>();
    k4_attn<<<dim3(HEADS, N_IMG * P2), 128>>>();
    k5_out<<<dim3(16, P2, N_IMG), 256>>>(w_lepe, b_lepe, out);
}

// round 5
// speedup vs baseline: 4.0486x; 2.1260x over previous
#include <cuda_runtime.h>
#include <cstdint>

// ---------------------------------------------------------------------------
// DeBiLevelRoutingAttention block. Round 5 (= R4 resubmit; infra failure).
// k4 attention moved onto mma.sync TF32 tensor cores.
// x:(16,512,56,56)  w_qkv:(1536,512)  b_qkv:(1536)  w_lepe:(512,1,3,3) b_lepe:(512)
// ---------------------------------------------------------------------------

#define N_IMG  16
#define C_DIM  512
#define H_IMG  56
#define W_IMG  56
#define HW     3136
#define QKC    512
#define NWIN   7
#define P2     49
#define W2     64
#define TOPK   4
#define HEADS  8
#define HD     64
#define SCALE  0.04419417382415922f   // 512^-0.5

// ----------------------------- scratch ------------------------------------
__device__ float g_q [(size_t)N_IMG * P2 * W2 * C_DIM];
__device__ float g_kv[(size_t)N_IMG * P2 * W2 * 1024];
__device__ float g_ao[(size_t)N_IMG * P2 * W2 * C_DIM];
__device__ float g_qwin[(size_t)N_IMG * P2 * C_DIM];
__device__ float g_kwin[(size_t)N_IMG * P2 * C_DIM];
__device__ int   g_idx [N_IMG * P2 * TOPK];

// ----------------------------- helpers ------------------------------------
__device__ __forceinline__ uint32_t f2tf32(float f) {
    uint32_t r;
    asm("cvt.rna.tf32.f32 %0, %1;" : "=r"(r) : "f"(f));
    return r;
}
__device__ __forceinline__ void mma_tf32(float c[4], const uint32_t a[4],
                                         uint32_t b0, uint32_t b1) {
    asm volatile(
        "mma.sync.aligned.m16n8k8.row.col.f32.tf32.tf32.f32 "
        "{%0,%1,%2,%3}, {%4,%5,%6,%7}, {%8,%9}, {%0,%1,%2,%3};"
        : "+f"(c[0]), "+f"(c[1]), "+f"(c[2]), "+f"(c[3])
        : "r"(a[0]), "r"(a[1]), "r"(a[2]), "r"(a[3]), "r"(b0), "r"(b1));
}

// ===========================================================================
// Kernel 1: QKV GEMM, TF32 mma.sync.  C[50176][1536] = A[M][512] @ B[1536][512]^T
// Block tile 128x128, K-chunk 32, double-buffered smem + register prefetch.
// ===========================================================================
#define K1_PITCH 136
#define K1_STG   (32 * K1_PITCH)
#define K1_SMEMB (4 * K1_STG * 4)

__global__ __launch_bounds__(256) void k1_qkv_mma(const float* __restrict__ x,
                                                  const float* __restrict__ w,
                                                  const float* __restrict__ bqkv) {
    extern __shared__ float sm[];
    float* As = sm;
    float* Bs = sm + 2 * K1_STG;

    const int t  = threadIdx.x;
    const int o0 = blockIdx.x * 128;
    const int m0 = blockIdx.y * 128;

    const int akr = t >> 3;
    const int am4 = (t & 7) * 4;
    const int bor = t >> 1;
    const int bk  = (t & 1) * 16;

    const int wid = t >> 5, lane = t & 31;
    const int mw = (wid & 3) * 32;
    const int nw = (wid >> 2) * 64;
    const int lq = lane & 3;
    const int lr = lane >> 2;

    float c[2][8][4];
#pragma unroll
    for (int mt = 0; mt < 2; mt++)
#pragma unroll
        for (int nt = 0; nt < 8; nt++)
#pragma unroll
            for (int i = 0; i < 4; i++) c[mt][nt][i] = 0.f;

    float4 aR[4], bR[4];
#pragma unroll
    for (int i = 0; i < 4; i++) {
        int m = m0 + am4 + i * 32;
        int n = m / HW, hw = m - n * HW;
        aR[i] = *(const float4*)(x + (size_t)n * (C_DIM * HW) + (size_t)akr * HW + hw);
        bR[i] = *(const float4*)(w + (size_t)(o0 + bor) * C_DIM + bk + i * 4);
    }

    for (int kc = 0; kc < 16; kc++) {
        const int st = kc & 1;
        float* A = As + st * K1_STG;
        float* B = Bs + st * K1_STG;
#pragma unroll
        for (int i = 0; i < 4; i++) {
            uint32_t* d = (uint32_t*)&A[akr * K1_PITCH + am4 + i * 32];
            uint32_t r0 = f2tf32(aR[i].x), r1 = f2tf32(aR[i].y);
            uint32_t r2 = f2tf32(aR[i].z), r3 = f2tf32(aR[i].w);
            asm volatile("st.shared.v4.b32 [%0], {%1,%2,%3,%4};"
                         :: "l"(d), "r"(r0), "r"(r1), "r"(r2), "r"(r3) : "memory");
            uint32_t* bd = (uint32_t*)B;
            bd[(bk + i * 4 + 0) * K1_PITCH + bor] = f2tf32(bR[i].x);
            bd[(bk + i * 4 + 1) * K1_PITCH + bor] = f2tf32(bR[i].y);
            bd[(bk + i * 4 + 2) * K1_PITCH + bor] = f2tf32(bR[i].z);
            bd[(bk + i * 4 + 3) * K1_PITCH + bor] = f2tf32(bR[i].w);
        }
        __syncthreads();
        if (kc < 15) {
            const int k0 = (kc + 1) * 32;
#pragma unroll
            for (int i = 0; i < 4; i++) {
                int m = m0 + am4 + i * 32;
                int n = m / HW, hw = m - n * HW;
                aR[i] = *(const float4*)(x + (size_t)n * (C_DIM * HW) + (size_t)(k0 + akr) * HW + hw);
                bR[i] = *(const float4*)(w + (size_t)(o0 + bor) * C_DIM + k0 + bk + i * 4);
            }
        }
        const uint32_t* Au = (const uint32_t*)A;
        const uint32_t* Bu = (const uint32_t*)B;
#pragma unroll
        for (int ks = 0; ks < 4; ks++) {
            const int kk = ks * 8;
            uint32_t a[2][4];
#pragma unroll
            for (int mt = 0; mt < 2; mt++) {
                const int mb = mw + mt * 16 + lr;
                a[mt][0] = Au[(kk + lq)     * K1_PITCH + mb];
                a[mt][1] = Au[(kk + lq)     * K1_PITCH + mb + 8];
                a[mt][2] = Au[(kk + 4 + lq) * K1_PITCH + mb];
                a[mt][3] = Au[(kk + 4 + lq) * K1_PITCH + mb + 8];
            }
#pragma unroll
            for (int nt = 0; nt < 8; nt++) {
                const int nb = nw + nt * 8 + lr;
                uint32_t b0 = Bu[(kk + lq)     * K1_PITCH + nb];
                uint32_t b1 = Bu[(kk + 4 + lq) * K1_PITCH + nb];
                mma_tf32(c[0][nt], a[0], b0, b1);
                mma_tf32(c[1][nt], a[1], b0, b1);
            }
        }
        __syncthreads();
    }

    const bool isq = (o0 < QKC);
#pragma unroll
    for (int mt = 0; mt < 2; mt++) {
#pragma unroll
        for (int half = 0; half < 2; half++) {
            const int row = mw + mt * 16 + lr + half * 8;
            const int m   = m0 + row;
            const int n   = m / HW;
            const int hw  = m - n * HW;
            const int h   = hw / W_IMG;
            const int wp  = hw - h * W_IMG;
            const int p   = (h >> 3) * NWIN + (wp >> 3);
            const int pix = ((h & 7) << 3) + (wp & 7);
            const size_t base = (size_t)((n * P2 + p) * W2 + pix);
            float* dst = isq ? (g_q + base * C_DIM + o0)
                             : (g_kv + base * 1024 + (o0 - QKC));
#pragma unroll
            for (int nt = 0; nt < 8; nt++) {
                const int col = nw + nt * 8 + lq * 2;
                float2 v;
                v.x = c[mt][nt][half * 2 + 0] + bqkv[o0 + col];
                v.y = c[mt][nt][half * 2 + 1] + bqkv[o0 + col + 1];
                *(float2*)(dst + col) = v;
            }
        }
    }
}

// ===========================================================================
// Kernel 2: per-window means of q and k. grid 784, block 256.
// ===========================================================================
__global__ __launch_bounds__(256) void k2_mean() {
    const int np = blockIdx.x;
    const float* qb = g_q  + (size_t)np * W2 * C_DIM;
    const float* kb = g_kv + (size_t)np * W2 * 1024;
    for (int c = threadIdx.x; c < C_DIM; c += 256) {
        float sq = 0.f, sk = 0.f;
#pragma unroll 8
        for (int pix = 0; pix < W2; pix++) {
            sq += qb[(size_t)pix * C_DIM + c];
            sk += kb[(size_t)pix * 1024  + c];
        }
        g_qwin[(size_t)np * C_DIM + c] = sq * (1.f / 64.f);
        g_kwin[(size_t)np * C_DIM + c] = sk * (1.f / 64.f);
    }
}

// ===========================================================================
// Kernel 3: routing logits + top-4 set. grid 784, block 64.
// ===========================================================================
__global__ __launch_bounds__(64) void k3_route() {
    __shared__ float qs[512];
    __shared__ float lg[P2];
    const int np = blockIdx.x;
    const int n  = np / P2;
    const int t  = threadIdx.x;
    for (int c = t; c < 512; c += 64)
        qs[c] = g_qwin[(size_t)np * 512 + c] * SCALE;
    __syncthreads();
    if (t < P2) {
        const float4* kr = (const float4*)(g_kwin + (size_t)(n * P2 + t) * 512);
        float s = 0.f;
#pragma unroll 4
        for (int c4 = 0; c4 < 128; c4++) {
            float4 k4 = kr[c4];
            s += qs[c4 * 4 + 0] * k4.x + qs[c4 * 4 + 1] * k4.y +
                 qs[c4 * 4 + 2] * k4.z + qs[c4 * 4 + 3] * k4.w;
        }
        lg[t] = s;
    }
    __syncthreads();
    if (t == 0) {
        unsigned long long used = 0;
        for (int sel = 0; sel < TOPK; sel++) {
            float best = -1e30f; int bi = 0;
            for (int m = 0; m < P2; m++) {
                if ((used >> m) & 1ULL) continue;
                if (lg[m] > best) { best = lg[m]; bi = m; }
            }
            used |= 1ULL << bi;
            g_idx[np * TOPK + sel] = bi;
        }
    }
}

// ===========================================================================
// Kernel 4: attention on mma.sync TF32.  One block per (head, np).
// 4 warps x 16 q-rows; S = Q.K^T (m16n8k8, 8x8 tiles), online softmax in
// C-fragment, P rna-rounded to tf32 (consistent with l-sum), relayout via
// per-warp smem tile, then O += P.V.  smem: Q/K/P pitch 68, V pitch 72.
// ===========================================================================
#define QP 68
#define VP 72
#define K4_SMEMU (3 * 64 * QP + 64 * VP)      // u32 words
#define K4_SMEMB (K4_SMEMU * 4)

__global__ __launch_bounds__(128) void k4_attn_tc() {
    extern __shared__ uint32_t su[];
    uint32_t* Qs = su;                         // [64][68] tf32
    uint32_t* Ks = su + 64 * QP;               // [64][68] tf32
    uint32_t* Ps = su + 2 * 64 * QP;           // [64][68] tf32 (per-warp rows)
    uint32_t* Vs = su + 3 * 64 * QP;           // [64][72] tf32, [key][dim]

    const int head = blockIdx.x;
    const int np   = blockIdx.y;
    const int n    = np / P2;
    const int t    = threadIdx.x;
    const int wid  = t >> 5;
    const int lane = t & 31;
    const int mw   = wid * 16;
    const int lr   = lane >> 2;
    const int lq   = lane & 3;

    // ---- load Q tile (scaled, tf32) ----
    const size_t qbase = (size_t)np * W2 * C_DIM + head * HD;
#pragma unroll
    for (int i = 0; i < 8; i++) {
        int idx = i * 128 + t;                 // 1024 float4 slots
        int pix = idx >> 4;
        int c4  = (idx & 15) << 2;
        float4 v = *(const float4*)(g_q + qbase + (size_t)pix * C_DIM + c4);
        uint32_t* d = &Qs[pix * QP + c4];
        d[0] = f2tf32(v.x * SCALE); d[1] = f2tf32(v.y * SCALE);
        d[2] = f2tf32(v.z * SCALE); d[3] = f2tf32(v.w * SCALE);
    }

    float Of[8][4];
#pragma unroll
    for (int dt = 0; dt < 8; dt++)
#pragma unroll
        for (int i = 0; i < 4; i++) Of[dt][i] = 0.f;
    float mrun[2] = {-1e30f, -1e30f}, lrun[2] = {0.f, 0.f};

    for (int tsel = 0; tsel < TOPK; tsel++) {
        const int widx = g_idx[np * TOPK + tsel];
        const size_t kvbase = (size_t)(n * P2 + widx) * W2 * 1024 + head * HD;
        __syncthreads();                        // prev window compute done
#pragma unroll
        for (int i = 0; i < 8; i++) {
            int idx = i * 128 + t;
            int pix = idx >> 4;
            int c4  = (idx & 15) << 2;
            float4 kvK = *(const float4*)(g_kv + kvbase + (size_t)pix * 1024 + c4);
            float4 kvV = *(const float4*)(g_kv + kvbase + (size_t)pix * 1024 + 512 + c4);
            uint32_t* kd = &Ks[pix * QP + c4];
            kd[0] = f2tf32(kvK.x); kd[1] = f2tf32(kvK.y);
            kd[2] = f2tf32(kvK.z); kd[3] = f2tf32(kvK.w);
            uint32_t* vd = &Vs[pix * VP + c4];
            vd[0] = f2tf32(kvV.x); vd[1] = f2tf32(kvV.y);
            vd[2] = f2tf32(kvV.z); vd[3] = f2tf32(kvV.w);
        }
        __syncthreads();

        // ---- S = Q.K^T : per warp 16 rows x 64 keys ----
        float sf[8][4];
#pragma unroll
        for (int nt = 0; nt < 8; nt++)
#pragma unroll
            for (int i = 0; i < 4; i++) sf[nt][i] = 0.f;
#pragma unroll
        for (int ks = 0; ks < 8; ks++) {
            const int kk = ks * 8;
            uint32_t a[4];
            a[0] = Qs[(mw + lr)     * QP + kk + lq];
            a[1] = Qs[(mw + lr + 8) * QP + kk + lq];
            a[2] = Qs[(mw + lr)     * QP + kk + 4 + lq];
            a[3] = Qs[(mw + lr + 8) * QP + kk + 4 + lq];
#pragma unroll
            for (int nt = 0; nt < 8; nt++) {
                uint32_t b0 = Ks[(nt * 8 + lr) * QP + kk + lq];
                uint32_t b1 = Ks[(nt * 8 + lr) * QP + kk + 4 + lq];
                mma_tf32(sf[nt], a, b0, b1);
            }
        }

        // ---- online softmax (rows lr / lr+8) ----
        float mx0 = -1e30f, mx1 = -1e30f;
#pragma unroll
        for (int nt = 0; nt < 8; nt++) {
            mx0 = fmaxf(mx0, fmaxf(sf[nt][0], sf[nt][1]));
            mx1 = fmaxf(mx1, fmaxf(sf[nt][2], sf[nt][3]));
        }
        mx0 = fmaxf(mx0, __shfl_xor_sync(0xffffffffu, mx0, 1));
        mx0 = fmaxf(mx0, __shfl_xor_sync(0xffffffffu, mx0, 2));
        mx1 = fmaxf(mx1, __shfl_xor_sync(0xffffffffu, mx1, 1));
        mx1 = fmaxf(mx1, __shfl_xor_sync(0xffffffffu, mx1, 2));
        const float mn0 = fmaxf(mrun[0], mx0);
        const float mn1 = fmaxf(mrun[1], mx1);
        const float cor0 = __expf(mrun[0] - mn0);
        const float cor1 = __expf(mrun[1] - mn1);
        float ls0 = 0.f, ls1 = 0.f;
#pragma unroll
        for (int nt = 0; nt < 8; nt++) {
            uint32_t p00 = f2tf32(__expf(sf[nt][0] - mn0));
            uint32_t p01 = f2tf32(__expf(sf[nt][1] - mn0));
            uint32_t p10 = f2tf32(__expf(sf[nt][2] - mn1));
            uint32_t p11 = f2tf32(__expf(sf[nt][3] - mn1));
            ls0 += __uint_as_float(p00) + __uint_as_float(p01);
            ls1 += __uint_as_float(p10) + __uint_as_float(p11);
            uint32_t* pr0 = &Ps[(mw + lr)     * QP + nt * 8 + lq * 2];
            uint32_t* pr1 = &Ps[(mw + lr + 8) * QP + nt * 8 + lq * 2];
            pr0[0] = p00; pr0[1] = p01;
            pr1[0] = p10; pr1[1] = p11;
        }
        ls0 += __shfl_xor_sync(0xffffffffu, ls0, 1);
        ls0 += __shfl_xor_sync(0xffffffffu, ls0, 2);
        ls1 += __shfl_xor_sync(0xffffffffu, ls1, 1);
        ls1 += __shfl_xor_sync(0xffffffffu, ls1, 2);
        lrun[0] = lrun[0] * cor0 + ls0;
        lrun[1] = lrun[1] * cor1 + ls1;
        mrun[0] = mn0; mrun[1] = mn1;
#pragma unroll
        for (int dt = 0; dt < 8; dt++) {
            Of[dt][0] *= cor0; Of[dt][1] *= cor0;
            Of[dt][2] *= cor1; Of[dt][3] *= cor1;
        }
        __syncwarp();

        // ---- O += P.V : k = 64 keys, n = 64 dims ----
#pragma unroll
        for (int ks = 0; ks < 8; ks++) {
            const int kk = ks * 8;
            uint32_t a[4];
            a[0] = Ps[(mw + lr)     * QP + kk + lq];
            a[1] = Ps[(mw + lr + 8) * QP + kk + lq];
            a[2] = Ps[(mw + lr)     * QP + kk + 4 + lq];
            a[3] = Ps[(mw + lr + 8) * QP + kk + 4 + lq];
#pragma unroll
            for (int dt = 0; dt < 8; dt++) {
                uint32_t b0 = Vs[(kk + lq)     * VP + dt * 8 + lr];
                uint32_t b1 = Vs[(kk + 4 + lq) * VP + dt * 8 + lr];
                mma_tf32(Of[dt], a, b0, b1);
            }
        }
    }

    // ---- write O / l ----
    const float inv0 = 1.f / lrun[0];
    const float inv1 = 1.f / lrun[1];
    const size_t obase = (size_t)np * W2 * C_DIM + head * HD;
    float* d0 = g_ao + obase + (size_t)(mw + lr)     * C_DIM;
    float* d1 = g_ao + obase + (size_t)(mw + lr + 8) * C_DIM;
#pragma unroll
    for (int dt = 0; dt < 8; dt++) {
        const int col = dt * 8 + lq * 2;
        *(float2*)(d0 + col) = make_float2(Of[dt][0] * inv0, Of[dt][1] * inv0);
        *(float2*)(d1 + col) = make_float2(Of[dt][2] * inv1, Of[dt][3] * inv1);
    }
}

// ===========================================================================
// Kernel 5: LePE depthwise 3x3 + attn out, NCHW transpose.
// ===========================================================================
__global__ __launch_bounds__(256) void k5_out(const float* __restrict__ wlepe,
                                              const float* __restrict__ blepe,
                                              float* __restrict__ out) {
    __shared__ float stage[64 * 36];
    const int cb = blockIdx.x;
    const int p  = blockIdx.y;
    const int n  = blockIdx.z;
    const int c0 = cb * 32;
    const int t  = threadIdx.x;
    const int c  = t & 31;
    const int pr = t >> 5;

    float wl[9];
#pragma unroll
    for (int k = 0; k < 9; k++) wl[k] = wlepe[(c0 + c) * 9 + k];
    const float bias = blepe[c0 + c];

    const int wh0 = (p / NWIN) * 8;
    const int ww0 = (p % NWIN) * 8;

    for (int pg = 0; pg < 8; pg++) {
        int pix = pg * 8 + pr;
        int ih = pix >> 3, iw = pix & 7;
        int h = wh0 + ih, w = ww0 + iw;
        float acc = bias;
#pragma unroll
        for (int kh = 0; kh < 3; kh++) {
            int hh = h + kh - 1;
            if (hh < 0 || hh >= H_IMG) continue;
#pragma unroll
            for (int kw = 0; kw < 3; kw++) {
                int ww = w + kw - 1;
                if (ww < 0 || ww >= W_IMG) continue;
                int pp   = (hh >> 3) * NWIN + (ww >> 3);
                int ppix = ((hh & 7) << 3) + (ww & 7);
                float vv = g_kv[((size_t)(n * P2 + pp) * W2 + ppix) * 1024 + 512 + c0 + c];
                acc += vv * wl[kh * 3 + kw];
            }
        }
        acc += g_ao[((size_t)(n * P2 + p) * W2 + pix) * C_DIM + c0 + c];
        stage[pix * 36 + c] = acc;
    }
    __syncthreads();

    const int wc = t >> 3;
    const int wx = t & 7;
    const size_t obase = ((size_t)n * C_DIM + c0 + wc) * HW;
    for (int h = 0; h < 8; h++) {
        out[obase + (size_t)(wh0 + h) * W_IMG + ww0 + wx] = stage[(h * 8 + wx) * 36 + wc];
    }
}

// ===========================================================================
extern "C" void kernel_launch(void* const* d_in, const int* in_sizes, int n_in,
                              void* d_out, int out_size) {
    const float* x      = (const float*)d_in[0];
    const float* w_qkv  = (const float*)d_in[1];
    const float* b_qkv  = (const float*)d_in[2];
    const float* w_lepe = (const float*)d_in[3];
    const float* b_lepe = (const float*)d_in[4];
    float* out = (float*)d_out;

    cudaFuncSetAttribute(k1_qkv_mma, cudaFuncAttributeMaxDynamicSharedMemorySize, K1_SMEMB);
    cudaFuncSetAttribute(k4_attn_tc, cudaFuncAttributeMaxDynamicSharedMemorySize, K4_SMEMB);

    k1_qkv_mma<<<dim3(12, 392), 256, K1_SMEMB>>>(x, w_qkv, b_qkv);
    k2_mean<<<784, 256>>>();
    k3_route<<<784, 64>>>();
    k4_attn_tc<<<dim3(HEADS, N_IMG * P2), 128, K4_SMEMB>>>();
    k5_out<<<dim3(16, P2, N_IMG), 256>>>(w_lepe, b_lepe, out);
}

// round 6
// speedup vs baseline: 4.5140x; 1.1149x over previous
#include <cuda_runtime.h>
#include <cuda_fp16.h>
#include <cstdint>

// ---------------------------------------------------------------------------
// DeBiLevelRoutingAttention block. Round 6: k1 + k4 on FP16 mma (m16n8k16).
// fp16 mantissa == tf32 mantissa (10 bits) -> same accuracy, 2x MACs/instr.
// x:(16,512,56,56)  w_qkv:(1536,512)  b_qkv:(1536)  w_lepe:(512,1,3,3) b_lepe:(512)
// ---------------------------------------------------------------------------

#define N_IMG  16
#define C_DIM  512
#define H_IMG  56
#define W_IMG  56
#define HW     3136
#define QKC    512
#define NWIN   7
#define P2     49
#define W2     64
#define TOPK   4
#define HEADS  8
#define HD     64
#define SCALE  0.04419417382415922f   // 512^-0.5

// ----------------------------- scratch ------------------------------------
__device__ float g_q [(size_t)N_IMG * P2 * W2 * C_DIM];
__device__ float g_kv[(size_t)N_IMG * P2 * W2 * 1024];
__device__ float g_ao[(size_t)N_IMG * P2 * W2 * C_DIM];
__device__ float g_qwin[(size_t)N_IMG * P2 * C_DIM];
__device__ float g_kwin[(size_t)N_IMG * P2 * C_DIM];
__device__ int   g_idx [N_IMG * P2 * TOPK];

// ----------------------------- helpers ------------------------------------
__device__ __forceinline__ uint32_t pack2(float lo, float hi) {
    __half2 h = __floats2half2_rn(lo, hi);
    return *reinterpret_cast<uint32_t*>(&h);
}
__device__ __forceinline__ void mma_f16(float c[4], const uint32_t a[4],
                                        uint32_t b0, uint32_t b1) {
    asm volatile(
        "mma.sync.aligned.m16n8k16.row.col.f32.f16.f16.f32 "
        "{%0,%1,%2,%3}, {%4,%5,%6,%7}, {%8,%9}, {%0,%1,%2,%3};"
        : "+f"(c[0]), "+f"(c[1]), "+f"(c[2]), "+f"(c[3])
        : "r"(a[0]), "r"(a[1]), "r"(a[2]), "r"(a[3]), "r"(b0), "r"(b1));
}

// ===========================================================================
// Kernel 1: QKV GEMM, FP16 mma m16n8k16. C[50176][1536] = A[M][512]@B[1536][512]^T
// Block tile 128x128, K-chunk 32 (= 16 half2 kpair-rows), double-buffered smem.
// Smem tiles: [kpair][m] / [kpair][o] as half2 (u32), pitch 132 (conflict-free).
// 8 warps = 4(M) x 2(N); warp tile 32x64; fused bias + window scatter epilogue.
// ===========================================================================
#define K1_P2   132                    // u32 per kpair row
#define K1_STG2 (16 * K1_P2)           // u32 per stage
#define K1_SMEMB (4 * K1_STG2 * 4)     // A x2 + B x2

__global__ __launch_bounds__(256) void k1_qkv_mma(const float* __restrict__ x,
                                                  const float* __restrict__ w,
                                                  const float* __restrict__ bqkv) {
    extern __shared__ uint32_t smu[];
    uint32_t* As = smu;                // [2][16][132]
    uint32_t* Bs = smu + 2 * K1_STG2;  // [2][16][132]

    const int t  = threadIdx.x;
    const int o0 = blockIdx.x * 128;
    const int m0 = blockIdx.y * 128;

    // A loader: kpair = t>>4 (0..15), 8 m's at (t&15)*8
    const int akp = t >> 4;
    const int am8 = (t & 15) * 8;
    const int mA  = m0 + am8;
    const int nA  = mA / HW;
    const int hwA = mA - nA * HW;
    const float* ax = x + (size_t)nA * (C_DIM * HW) + hwA;

    // B loader: o-row = t>>1, k-half = (t&1)*16
    const int bo  = t >> 1;
    const int bkh = (t & 1) * 16;
    const float* bptr = w + (size_t)(o0 + bo) * C_DIM + bkh;

    const int wid = t >> 5, lane = t & 31;
    const int mw = (wid & 3) * 32;
    const int nw = (wid >> 2) * 64;
    const int lq = lane & 3;
    const int lr = lane >> 2;

    float c[2][8][4];
#pragma unroll
    for (int mt = 0; mt < 2; mt++)
#pragma unroll
        for (int nt = 0; nt < 8; nt++)
#pragma unroll
            for (int i = 0; i < 4; i++) c[mt][nt][i] = 0.f;

    float4 aR[4], bR[4];
    // prefetch chunk 0
    {
        const float* a0p = ax + (size_t)(2 * akp) * HW;
        aR[0] = *(const float4*)(a0p);
        aR[1] = *(const float4*)(a0p + 4);
        aR[2] = *(const float4*)(a0p + HW);
        aR[3] = *(const float4*)(a0p + HW + 4);
#pragma unroll
        for (int i = 0; i < 4; i++) bR[i] = *(const float4*)(bptr + i * 4);
    }

    for (int kc = 0; kc < 16; kc++) {
        const int st = kc & 1;
        uint32_t* A = As + st * K1_STG2;
        uint32_t* B = Bs + st * K1_STG2;
        // ---- store current chunk as half2 ----
        {
            uint32_t h0 = pack2(aR[0].x, aR[2].x), h1 = pack2(aR[0].y, aR[2].y);
            uint32_t h2 = pack2(aR[0].z, aR[2].z), h3 = pack2(aR[0].w, aR[2].w);
            uint32_t h4 = pack2(aR[1].x, aR[3].x), h5 = pack2(aR[1].y, aR[3].y);
            uint32_t h6 = pack2(aR[1].z, aR[3].z), h7 = pack2(aR[1].w, aR[3].w);
            uint32_t* d = &A[akp * K1_P2 + am8];
            asm volatile("st.shared.v4.b32 [%0], {%1,%2,%3,%4};"
                         :: "l"(d), "r"(h0), "r"(h1), "r"(h2), "r"(h3) : "memory");
            asm volatile("st.shared.v4.b32 [%0], {%1,%2,%3,%4};"
                         :: "l"(d + 4), "r"(h4), "r"(h5), "r"(h6), "r"(h7) : "memory");
#pragma unroll
            for (int i = 0; i < 4; i++) {
                const int kp = (bkh >> 1) + 2 * i;
                B[kp * K1_P2 + bo]       = pack2(bR[i].x, bR[i].y);
                B[(kp + 1) * K1_P2 + bo] = pack2(bR[i].z, bR[i].w);
            }
        }
        __syncthreads();
        if (kc < 15) {      // prefetch next
            const int k0 = (kc + 1) * 32;
            const float* a0p = ax + (size_t)(k0 + 2 * akp) * HW;
            aR[0] = *(const float4*)(a0p);
            aR[1] = *(const float4*)(a0p + 4);
            aR[2] = *(const float4*)(a0p + HW);
            aR[3] = *(const float4*)(a0p + HW + 4);
#pragma unroll
            for (int i = 0; i < 4; i++) bR[i] = *(const float4*)(bptr + k0 + i * 4);
        }
        // ---- compute: 2 mma k-steps of k16 (8 kpair rows each) ----
#pragma unroll
        for (int ks = 0; ks < 2; ks++) {
            const int kp = ks * 8;
            uint32_t a[2][4];
#pragma unroll
            for (int mt = 0; mt < 2; mt++) {
                const int mb = mw + mt * 16 + lr;
                a[mt][0] = A[(kp + lq)     * K1_P2 + mb];
                a[mt][1] = A[(kp + lq)     * K1_P2 + mb + 8];
                a[mt][2] = A[(kp + 4 + lq) * K1_P2 + mb];
                a[mt][3] = A[(kp + 4 + lq) * K1_P2 + mb + 8];
            }
#pragma unroll
            for (int nt = 0; nt < 8; nt++) {
                const int nb = nw + nt * 8 + lr;
                uint32_t b0 = B[(kp + lq)     * K1_P2 + nb];
                uint32_t b1 = B[(kp + 4 + lq) * K1_P2 + nb];
                mma_f16(c[0][nt], a[0], b0, b1);
                mma_f16(c[1][nt], a[1], b0, b1);
            }
        }
        __syncthreads();
    }

    // ----- epilogue: bias + window scatter -----
    const bool isq = (o0 < QKC);
#pragma unroll
    for (int mt = 0; mt < 2; mt++) {
#pragma unroll
        for (int half = 0; half < 2; half++) {
            const int row = mw + mt * 16 + lr + half * 8;
            const int m   = m0 + row;
            const int n   = m / HW;
            const int hw  = m - n * HW;
            const int h   = hw / W_IMG;
            const int wp  = hw - h * W_IMG;
            const int p   = (h >> 3) * NWIN + (wp >> 3);
            const int pix = ((h & 7) << 3) + (wp & 7);
            const size_t base = (size_t)((n * P2 + p) * W2 + pix);
            float* dst = isq ? (g_q + base * C_DIM + o0)
                             : (g_kv + base * 1024 + (o0 - QKC));
#pragma unroll
            for (int nt = 0; nt < 8; nt++) {
                const int col = nw + nt * 8 + lq * 2;
                float2 v;
                v.x = c[mt][nt][half * 2 + 0] + bqkv[o0 + col];
                v.y = c[mt][nt][half * 2 + 1] + bqkv[o0 + col + 1];
                *(float2*)(dst + col) = v;
            }
        }
    }
}

// ===========================================================================
// Kernel 2: per-window means of q and k. grid 784, block 256.
// ===========================================================================
__global__ __launch_bounds__(256) void k2_mean() {
    const int np = blockIdx.x;
    const float* qb = g_q  + (size_t)np * W2 * C_DIM;
    const float* kb = g_kv + (size_t)np * W2 * 1024;
    for (int c = threadIdx.x; c < C_DIM; c += 256) {
        float sq = 0.f, sk = 0.f;
#pragma unroll 8
        for (int pix = 0; pix < W2; pix++) {
            sq += qb[(size_t)pix * C_DIM + c];
            sk += kb[(size_t)pix * 1024  + c];
        }
        g_qwin[(size_t)np * C_DIM + c] = sq * (1.f / 64.f);
        g_kwin[(size_t)np * C_DIM + c] = sk * (1.f / 64.f);
    }
}

// ===========================================================================
// Kernel 3: routing logits + top-4 set. grid 784, block 64.
// ===========================================================================
__global__ __launch_bounds__(64) void k3_route() {
    __shared__ float qs[512];
    __shared__ float lg[P2];
    const int np = blockIdx.x;
    const int n  = np / P2;
    const int t  = threadIdx.x;
    for (int c = t; c < 512; c += 64)
        qs[c] = g_qwin[(size_t)np * 512 + c] * SCALE;
    __syncthreads();
    if (t < P2) {
        const float4* kr = (const float4*)(g_kwin + (size_t)(n * P2 + t) * 512);
        float s = 0.f;
#pragma unroll 4
        for (int c4 = 0; c4 < 128; c4++) {
            float4 k4 = kr[c4];
            s += qs[c4 * 4 + 0] * k4.x + qs[c4 * 4 + 1] * k4.y +
                 qs[c4 * 4 + 2] * k4.z + qs[c4 * 4 + 3] * k4.w;
        }
        lg[t] = s;
    }
    __syncthreads();
    if (t == 0) {
        unsigned long long used = 0;
        for (int sel = 0; sel < TOPK; sel++) {
            float best = -1e30f; int bi = 0;
            for (int m = 0; m < P2; m++) {
                if ((used >> m) & 1ULL) continue;
                if (lg[m] > best) { best = lg[m]; bi = m; }
            }
            used |= 1ULL << bi;
            g_idx[np * TOPK + sel] = bi;
        }
    }
}

// ===========================================================================
// Kernel 4: attention on FP16 mma m16n8k16. One block per (head, np).
// Q/K/P as half2 [row][dimpair] pitch 36; V as half2 [keypair][dim] pitch 68.
// 4 warps x 16 q-rows; online softmax; P packed directly from C-fragment.
// ===========================================================================
#define QP2 36
#define VP2 68
#define K4_Q  0
#define K4_K  (64 * QP2)
#define K4_P  (2 * 64 * QP2)
#define K4_V  (3 * 64 * QP2)
#define K4_SMEMB ((3 * 64 * QP2 + 32 * VP2) * 4)

__global__ __launch_bounds__(128) void k4_attn_tc() {
    extern __shared__ uint32_t su[];
    uint32_t* Qs = su + K4_Q;
    uint32_t* Ks = su + K4_K;
    uint32_t* Ps = su + K4_P;
    uint32_t* Vs = su + K4_V;

    const int head = blockIdx.x;
    const int np   = blockIdx.y;
    const int n    = np / P2;
    const int t    = threadIdx.x;
    const int wid  = t >> 5;
    const int lane = t & 31;
    const int mw   = wid * 16;
    const int lr   = lane >> 2;
    const int lq   = lane & 3;

    // ---- load Q tile (scaled, fp16 pairs) ----
    const size_t qbase = (size_t)np * W2 * C_DIM + head * HD;
#pragma unroll
    for (int i = 0; i < 4; i++) {
        int idx = i * 128 + t;                  // 512 slots: pix = idx>>3, 8 dims
        int pix = idx >> 3;
        int d8  = (idx & 7) * 8;
        const float* src = g_q + qbase + (size_t)pix * C_DIM + d8;
        float4 v0 = *(const float4*)(src);
        float4 v1 = *(const float4*)(src + 4);
        uint32_t h0 = pack2(v0.x * SCALE, v0.y * SCALE);
        uint32_t h1 = pack2(v0.z * SCALE, v0.w * SCALE);
        uint32_t h2 = pack2(v1.x * SCALE, v1.y * SCALE);
        uint32_t h3 = pack2(v1.z * SCALE, v1.w * SCALE);
        uint32_t* d = &Qs[pix * QP2 + (d8 >> 1)];
        asm volatile("st.shared.v4.b32 [%0], {%1,%2,%3,%4};"
                     :: "l"(d), "r"(h0), "r"(h1), "r"(h2), "r"(h3) : "memory");
    }

    float Of[8][4];
#pragma unroll
    for (int dt = 0; dt < 8; dt++)
#pragma unroll
        for (int i = 0; i < 4; i++) Of[dt][i] = 0.f;
    float mrun[2] = {-1e30f, -1e30f}, lrun[2] = {0.f, 0.f};

    for (int tsel = 0; tsel < TOPK; tsel++) {
        const int widx = g_idx[np * TOPK + tsel];
        const size_t kvbase = (size_t)(n * P2 + widx) * W2 * 1024 + head * HD;
        __syncthreads();                        // prev window compute done
        // K: [key][dimpair]
#pragma unroll
        for (int i = 0; i < 4; i++) {
            int idx = i * 128 + t;
            int pix = idx >> 3;
            int d8  = (idx & 7) * 8;
            const float* src = g_kv + kvbase + (size_t)pix * 1024 + d8;
            float4 v0 = *(const float4*)(src);
            float4 v1 = *(const float4*)(src + 4);
            uint32_t h0 = pack2(v0.x, v0.y), h1 = pack2(v0.z, v0.w);
            uint32_t h2 = pack2(v1.x, v1.y), h3 = pack2(v1.z, v1.w);
            uint32_t* d = &Ks[pix * QP2 + (d8 >> 1)];
            asm volatile("st.shared.v4.b32 [%0], {%1,%2,%3,%4};"
                         :: "l"(d), "r"(h0), "r"(h1), "r"(h2), "r"(h3) : "memory");
        }
        // V: [keypair][dim] (pack across keys)
#pragma unroll
        for (int i = 0; i < 4; i++) {
            int idx = i * 128 + t;
            int kp  = idx >> 4;                 // 0..31
            int d4  = (idx & 15) * 4;
            const float* srcA = g_kv + kvbase + (size_t)(2 * kp)     * 1024 + 512 + d4;
            const float* srcB = g_kv + kvbase + (size_t)(2 * kp + 1) * 1024 + 512 + d4;
            float4 vA = *(const float4*)(srcA);
            float4 vB = *(const float4*)(srcB);
            uint32_t h0 = pack2(vA.x, vB.x), h1 = pack2(vA.y, vB.y);
            uint32_t h2 = pack2(vA.z, vB.z), h3 = pack2(vA.w, vB.w);
            uint32_t* d = &Vs[kp * VP2 + d4];
            asm volatile("st.shared.v4.b32 [%0], {%1,%2,%3,%4};"
                         :: "l"(d), "r"(h0), "r"(h1), "r"(h2), "r"(h3) : "memory");
        }
        __syncthreads();

        // ---- S = Q.K^T : per warp 16 rows x 64 keys, 4 k16 steps ----
        float sf[8][4];
#pragma unroll
        for (int nt = 0; nt < 8; nt++)
#pragma unroll
            for (int i = 0; i < 4; i++) sf[nt][i] = 0.f;
#pragma unroll
        for (int ks = 0; ks < 4; ks++) {
            const int kp = ks * 8;
            uint32_t a[4];
            a[0] = Qs[(mw + lr)     * QP2 + kp + lq];
            a[1] = Qs[(mw + lr + 8) * QP2 + kp + lq];
            a[2] = Qs[(mw + lr)     * QP2 + kp + 4 + lq];
            a[3] = Qs[(mw + lr + 8) * QP2 + kp + 4 + lq];
#pragma unroll
            for (int nt = 0; nt < 8; nt++) {
                uint32_t b0 = Ks[(nt * 8 + lr) * QP2 + kp + lq];
                uint32_t b1 = Ks[(nt * 8 + lr) * QP2 + kp + 4 + lq];
                mma_f16(sf[nt], a, b0, b1);
            }
        }

        // ---- online softmax (rows lr / lr+8) ----
        float mx0 = -1e30f, mx1 = -1e30f;
#pragma unroll
        for (int nt = 0; nt < 8; nt++) {
            mx0 = fmaxf(mx0, fmaxf(sf[nt][0], sf[nt][1]));
            mx1 = fmaxf(mx1, fmaxf(sf[nt][2], sf[nt][3]));
        }
        mx0 = fmaxf(mx0, __shfl_xor_sync(0xffffffffu, mx0, 1));
        mx0 = fmaxf(mx0, __shfl_xor_sync(0xffffffffu, mx0, 2));
        mx1 = fmaxf(mx1, __shfl_xor_sync(0xffffffffu, mx1, 1));
        mx1 = fmaxf(mx1, __shfl_xor_sync(0xffffffffu, mx1, 2));
        const float mn0 = fmaxf(mrun[0], mx0);
        const float mn1 = fmaxf(mrun[1], mx1);
        const float cor0 = __expf(mrun[0] - mn0);
        const float cor1 = __expf(mrun[1] - mn1);
        float ls0 = 0.f, ls1 = 0.f;
#pragma unroll
        for (int nt = 0; nt < 8; nt++) {
            __half2 hp0 = __floats2half2_rn(__expf(sf[nt][0] - mn0), __expf(sf[nt][1] - mn0));
            __half2 hp1 = __floats2half2_rn(__expf(sf[nt][2] - mn1), __expf(sf[nt][3] - mn1));
            float2 f0 = __half22float2(hp0);
            float2 f1 = __half22float2(hp1);
            ls0 += f0.x + f0.y;
            ls1 += f1.x + f1.y;
            Ps[(mw + lr)     * QP2 + nt * 4 + lq] = *reinterpret_cast<uint32_t*>(&hp0);
            Ps[(mw + lr + 8) * QP2 + nt * 4 + lq] = *reinterpret_cast<uint32_t*>(&hp1);
        }
        ls0 += __shfl_xor_sync(0xffffffffu, ls0, 1);
        ls0 += __shfl_xor_sync(0xffffffffu, ls0, 2);
        ls1 += __shfl_xor_sync(0xffffffffu, ls1, 1);
        ls1 += __shfl_xor_sync(0xffffffffu, ls1, 2);
        lrun[0] = lrun[0] * cor0 + ls0;
        lrun[1] = lrun[1] * cor1 + ls1;
        mrun[0] = mn0; mrun[1] = mn1;
#pragma unroll
        for (int dt = 0; dt < 8; dt++) {
            Of[dt][0] *= cor0; Of[dt][1] *= cor0;
            Of[dt][2] *= cor1; Of[dt][3] *= cor1;
        }
        __syncwarp();

        // ---- O += P.V : 4 k16 steps over 64 keys ----
#pragma unroll
        for (int ks = 0; ks < 4; ks++) {
            const int kp = ks * 8;
            uint32_t a[4];
            a[0] = Ps[(mw + lr)     * QP2 + kp + lq];
            a[1] = Ps[(mw + lr + 8) * QP2 + kp + lq];
            a[2] = Ps[(mw + lr)     * QP2 + kp + 4 + lq];
            a[3] = Ps[(mw + lr + 8) * QP2 + kp + 4 + lq];
#pragma unroll
            for (int dt = 0; dt < 8; dt++) {
                uint32_t b0 = Vs[(kp + lq)     * VP2 + dt * 8 + lr];
                uint32_t b1 = Vs[(kp + 4 + lq) * VP2 + dt * 8 + lr];
                mma_f16(Of[dt], a, b0, b1);
            }
        }
    }

    // ---- write O ----
    const float inv0 = 1.f / lrun[0];
    const float inv1 = 1.f / lrun[1];
    const size_t obase = (size_t)np * W2 * C_DIM + head * HD;
    float* d0 = g_ao + obase + (size_t)(mw + lr)     * C_DIM;
    float* d1 = g_ao + obase + (size_t)(mw + lr + 8) * C_DIM;
#pragma unroll
    for (int dt = 0; dt < 8; dt++) {
        const int col = dt * 8 + lq * 2;
        *(float2*)(d0 + col) = make_float2(Of[dt][0] * inv0, Of[dt][1] * inv0);
        *(float2*)(d1 + col) = make_float2(Of[dt][2] * inv1, Of[dt][3] * inv1);
    }
}

// ===========================================================================
// Kernel 5: LePE depthwise 3x3 + attn out, NCHW transpose.
// ===========================================================================
__global__ __launch_bounds__(256) void k5_out(const float* __restrict__ wlepe,
                                              const float* __restrict__ blepe,
                                              float* __restrict__ out) {
    __shared__ float stage[64 * 36];
    const int cb = blockIdx.x;
    const int p  = blockIdx.y;
    const int n  = blockIdx.z;
    const int c0 = cb * 32;
    const int t  = threadIdx.x;
    const int c  = t & 31;
    const int pr = t >> 5;

    float wl[9];
#pragma unroll
    for (int k = 0; k < 9; k++) wl[k] = wlepe[(c0 + c) * 9 + k];
    const float bias = blepe[c0 + c];

    const int wh0 = (p / NWIN) * 8;
    const int ww0 = (p % NWIN) * 8;

    for (int pg = 0; pg < 8; pg++) {
        int pix = pg * 8 + pr;
        int ih = pix >> 3, iw = pix & 7;
        int h = wh0 + ih, w = ww0 + iw;
        float acc = bias;
#pragma unroll
        for (int kh = 0; kh < 3; kh++) {
            int hh = h + kh - 1;
            if (hh < 0 || hh >= H_IMG) continue;
#pragma unroll
            for (int kw = 0; kw < 3; kw++) {
                int ww = w + kw - 1;
                if (ww < 0 || ww >= W_IMG) continue;
                int pp   = (hh >> 3) * NWIN + (ww >> 3);
                int ppix = ((hh & 7) << 3) + (ww & 7);
                float vv = g_kv[((size_t)(n * P2 + pp) * W2 + ppix) * 1024 + 512 + c0 + c];
                acc += vv * wl[kh * 3 + kw];
            }
        }
        acc += g_ao[((size_t)(n * P2 + p) * W2 + pix) * C_DIM + c0 + c];
        stage[pix * 36 + c] = acc;
    }
    __syncthreads();

    const int wc = t >> 3;
    const int wx = t & 7;
    const size_t obase = ((size_t)n * C_DIM + c0 + wc) * HW;
    for (int h = 0; h < 8; h++) {
        out[obase + (size_t)(wh0 + h) * W_IMG + ww0 + wx] = stage[(h * 8 + wx) * 36 + wc];
    }
}

// ===========================================================================
extern "C" void kernel_launch(void* const* d_in, const int* in_sizes, int n_in,
                              void* d_out, int out_size) {
    const float* x      = (const float*)d_in[0];
    const float* w_qkv  = (const float*)d_in[1];
    const float* b_qkv  = (const float*)d_in[2];
    const float* w_lepe = (const float*)d_in[3];
    const float* b_lepe = (const float*)d_in[4];
    float* out = (float*)d_out;

    cudaFuncSetAttribute(k1_qkv_mma, cudaFuncAttributeMaxDynamicSharedMemorySize, K1_SMEMB);
    cudaFuncSetAttribute(k4_attn_tc, cudaFuncAttributeMaxDynamicSharedMemorySize, K4_SMEMB);

    k1_qkv_mma<<<dim3(12, 392), 256, K1_SMEMB>>>(x, w_qkv, b_qkv);
    k2_mean<<<784, 256>>>();
    k3_route<<<784, 64>>>();
    k4_attn_tc<<<dim3(HEADS, N_IMG * P2), 128, K4_SMEMB>>>();
    k5_out<<<dim3(16, P2, N_IMG), 256>>>(w_lepe, b_lepe, out);
}

// round 7
// speedup vs baseline: 7.6873x; 1.7030x over previous
#include <cuda_runtime.h>
#include <cuda_fp16.h>
#include <cstdint>

// ---------------------------------------------------------------------------
// DeBiLevelRoutingAttention block. Round 7: cp.async + ldmatrix pipelines.
// k0 pre-converts x,w to fp16; k1 GEMM 4-stage cp.async + ldmatrix; k1 also
// emits fp16 q(scaled)/kv copies so k4 loads via cp.async + ldmatrix with
// P-fragments taken directly from softmax registers.
// ---------------------------------------------------------------------------

#define N_IMG  16
#define C_DIM  512
#define H_IMG  56
#define W_IMG  56
#define HW     3136
#define CHW    (C_DIM * HW)
#define QKC    512
#define NWIN   7
#define P2     49
#define W2     64
#define TOPK   4
#define HEADS  8
#define HD     64
#define SCALE  0.04419417382415922f   // 512^-0.5

// ----------------------------- scratch ------------------------------------
__device__ float g_q [(size_t)N_IMG * P2 * W2 * C_DIM];
__device__ float g_kv[(size_t)N_IMG * P2 * W2 * 1024];
__device__ float g_ao[(size_t)N_IMG * P2 * W2 * C_DIM];
__device__ float g_qwin[(size_t)N_IMG * P2 * C_DIM];
__device__ float g_kwin[(size_t)N_IMG * P2 * C_DIM];
__device__ int   g_idx [N_IMG * P2 * TOPK];
__device__ __align__(16) __half g_xh [(size_t)N_IMG * CHW];
__device__ __align__(16) __half g_wh [1536 * 512];
__device__ __align__(16) __half g_qh [(size_t)N_IMG * P2 * W2 * 512];
__device__ __align__(16) __half g_kvh[(size_t)N_IMG * P2 * W2 * 1024];

// ----------------------------- helpers ------------------------------------
__device__ __forceinline__ uint32_t pack2(float lo, float hi) {
    __half2 h = __floats2half2_rn(lo, hi);
    return *reinterpret_cast<uint32_t*>(&h);
}
__device__ __forceinline__ uint32_t smem_u32(const void* p) {
    return (uint32_t)__cvta_generic_to_shared(p);
}
__device__ __forceinline__ void mma_f16(float c[4], const uint32_t a[4],
                                        uint32_t b0, uint32_t b1) {
    asm volatile(
        "mma.sync.aligned.m16n8k16.row.col.f32.f16.f16.f32 "
        "{%0,%1,%2,%3}, {%4,%5,%6,%7}, {%8,%9}, {%0,%1,%2,%3};"
        : "+f"(c[0]), "+f"(c[1]), "+f"(c[2]), "+f"(c[3])
        : "r"(a[0]), "r"(a[1]), "r"(a[2]), "r"(a[3]), "r"(b0), "r"(b1));
}
#define CP_ASYNC16(dst, src) \
    asm volatile("cp.async.cg.shared.global [%0], [%1], 16;" \
                 :: "r"(dst), "l"(src) : "memory")
#define CP_COMMIT() asm volatile("cp.async.commit_group;" ::: "memory")
#define CP_WAIT(n)  asm volatile("cp.async.wait_group %0;" :: "n"(n) : "memory")
#define LDSM_X4(r, a) \
    asm volatile("ldmatrix.sync.aligned.m8n8.x4.shared.b16 {%0,%1,%2,%3}, [%4];" \
        : "=r"((r)[0]), "=r"((r)[1]), "=r"((r)[2]), "=r"((r)[3]) : "r"(a))
#define LDSM_X4T(r, a) \
    asm volatile("ldmatrix.sync.aligned.m8n8.x4.trans.shared.b16 {%0,%1,%2,%3}, [%4];" \
        : "=r"((r)[0]), "=r"((r)[1]), "=r"((r)[2]), "=r"((r)[3]) : "r"(a))

// ===========================================================================
// Kernel 0: convert x and w_qkv to fp16. grid-stride over float4s.
// ===========================================================================
__global__ __launch_bounds__(256) void k0_half(const float* __restrict__ x,
                                               const float* __restrict__ w) {
    const int i = blockIdx.x * 256 + threadIdx.x;
    const int NX4 = (N_IMG * CHW) >> 2;        // 6422528
    const int NW4 = (1536 * 512) >> 2;         // 196608
    if (i < NX4) {
        float4 v = ((const float4*)x)[i];
        uint32_t* d = (uint32_t*)g_xh;
        d[2 * i]     = pack2(v.x, v.y);
        d[2 * i + 1] = pack2(v.z, v.w);
    }
    if (i < NW4) {
        float4 v = ((const float4*)w)[i];
        uint32_t* d = (uint32_t*)g_wh;
        d[2 * i]     = pack2(v.x, v.y);
        d[2 * i + 1] = pack2(v.z, v.w);
    }
}

// ===========================================================================
// Kernel 1: QKV GEMM, fp16 mma + cp.async 4-stage + ldmatrix.
// A smem [k][m] 32x128 halves pitch 272B (ldmatrix.trans);
// B smem [n][k] 128x32 halves pitch 80B (ldmatrix).
// grid (12, 392), 256 thr, 8 warps = 4Mx2N, warp tile 32x64.
// Epilogue: bias + window scatter to fp32 g_q/g_kv AND fp16 g_qh/g_kvh.
// ===========================================================================
#define K1_ABYTES 8704                 // 32 * 272
#define K1_BBYTES 10240                // 128 * 80
#define K1_STAGE  (K1_ABYTES + K1_BBYTES)
#define K1_SMEM   (4 * K1_STAGE)       // 75776

__global__ __launch_bounds__(256) void k1_qkv_tc(const float* __restrict__ bqkv) {
    extern __shared__ char smc[];
    const uint32_t sb = smem_u32(smc);
    const int t  = threadIdx.x;
    const int o0 = blockIdx.x * 128;
    const int m0 = blockIdx.y * 128;

    // loader precompute
    const int m16h = (t & 15) * 8;
    const int kr0  = t >> 4;                   // 0..15
    const int mA   = m0 + m16h;
    const int nA   = mA / HW;
    const int hwA  = mA - nA * HW;
    const __half* axp = g_xh + (size_t)nA * CHW + hwA;
    const int bn0 = t >> 2;                    // 0..63
    const int bk8 = (t & 3) * 8;
    const __half* bw0 = g_wh + (size_t)(o0 + bn0) * 512 + bk8;

    const int wid = t >> 5, lane = t & 31;
    const int mw = (wid & 3) * 32;
    const int nw = (wid >> 2) * 64;
    const int grp = lane >> 3, li = lane & 7;
    const int a_k = li + ((grp & 2) ? 8 : 0);
    const int a_m = (grp & 1) ? 8 : 0;
    const int b_n = li + ((grp & 2) ? 8 : 0);
    const int b_k = (grp & 1) ? 8 : 0;
    const int lr = lane >> 2, lq = lane & 3;

    float c[2][8][4];
#pragma unroll
    for (int mt = 0; mt < 2; mt++)
#pragma unroll
        for (int nt = 0; nt < 8; nt++)
#pragma unroll
            for (int i = 0; i < 4; i++) c[mt][nt][i] = 0.f;

#define K1_ISSUE(kc_) do {                                                    \
    const int s_ = (kc_) & 3;                                                 \
    const uint32_t ab_ = sb + s_ * K1_STAGE;                                  \
    const uint32_t bb_ = ab_ + K1_ABYTES;                                     \
    CP_ASYNC16(ab_ + kr0 * 272 + m16h * 2,                                    \
               axp + (size_t)((kc_) * 32 + kr0) * HW);                        \
    CP_ASYNC16(ab_ + (16 + kr0) * 272 + m16h * 2,                             \
               axp + (size_t)((kc_) * 32 + 16 + kr0) * HW);                   \
    CP_ASYNC16(bb_ + bn0 * 80 + bk8 * 2, bw0 + (kc_) * 32);                   \
    CP_ASYNC16(bb_ + (64 + bn0) * 80 + bk8 * 2,                               \
               bw0 + 64 * 512 + (kc_) * 32);                                  \
} while (0)

    K1_ISSUE(0); CP_COMMIT();
    K1_ISSUE(1); CP_COMMIT();
    K1_ISSUE(2); CP_COMMIT();

    for (int kc = 0; kc < 16; kc++) {
        CP_WAIT(2);
        __syncthreads();
        if (kc + 3 < 16) { K1_ISSUE(kc + 3); }
        CP_COMMIT();
        const uint32_t ab = sb + (kc & 3) * K1_STAGE;
        const uint32_t bb = ab + K1_ABYTES;
#pragma unroll
        for (int ks = 0; ks < 2; ks++) {
            uint32_t a[2][4];
#pragma unroll
            for (int mt = 0; mt < 2; mt++)
                LDSM_X4T(a[mt], ab + (ks * 16 + a_k) * 272 + (mw + mt * 16 + a_m) * 2);
            uint32_t b[4][4];
#pragma unroll
            for (int ntp = 0; ntp < 4; ntp++)
                LDSM_X4(b[ntp], bb + (nw + ntp * 16 + b_n) * 80 + (ks * 16 + b_k) * 2);
#pragma unroll
            for (int ntp = 0; ntp < 4; ntp++) {
                mma_f16(c[0][2 * ntp],     a[0], b[ntp][0], b[ntp][1]);
                mma_f16(c[0][2 * ntp + 1], a[0], b[ntp][2], b[ntp][3]);
                mma_f16(c[1][2 * ntp],     a[1], b[ntp][0], b[ntp][1]);
                mma_f16(c[1][2 * ntp + 1], a[1], b[ntp][2], b[ntp][3]);
            }
        }
    }

    // ----- epilogue: bias + window scatter (fp32 + fp16 copies) -----
    const bool isq = (o0 < QKC);
#pragma unroll
    for (int mt = 0; mt < 2; mt++) {
#pragma unroll
        for (int half = 0; half < 2; half++) {
            const int row = mw + mt * 16 + lr + half * 8;
            const int m   = m0 + row;
            const int n   = m / HW;
            const int hw  = m - n * HW;
            const int h   = hw / W_IMG;
            const int wp  = hw - h * W_IMG;
            const int p   = (h >> 3) * NWIN + (wp >> 3);
            const int pix = ((h & 7) << 3) + (wp & 7);
            const size_t npix = (size_t)((n * P2 + p) * W2 + pix);
            float* dstf = isq ? (g_q + npix * 512 + o0)
                              : (g_kv + npix * 1024 + (o0 - QKC));
            uint32_t* dsth = isq ? ((uint32_t*)g_qh  + npix * 256 + (o0 >> 1))
                                 : ((uint32_t*)g_kvh + npix * 512 + ((o0 - QKC) >> 1));
#pragma unroll
            for (int nt = 0; nt < 8; nt++) {
                const int col = nw + nt * 8 + lq * 2;
                float vx = c[mt][nt][half * 2 + 0] + bqkv[o0 + col];
                float vy = c[mt][nt][half * 2 + 1] + bqkv[o0 + col + 1];
                *(float2*)(dstf + col) = make_float2(vx, vy);
                dsth[col >> 1] = isq ? pack2(vx * SCALE, vy * SCALE) : pack2(vx, vy);
            }
        }
    }
#undef K1_ISSUE
}

// ===========================================================================
// Kernel 2: per-window means of q and k (fp32). grid 784, block 256.
// ===========================================================================
__global__ __launch_bounds__(256) void k2_mean() {
    const int np = blockIdx.x;
    const float* qb = g_q  + (size_t)np * W2 * C_DIM;
    const float* kb = g_kv + (size_t)np * W2 * 1024;
    for (int c = threadIdx.x; c < C_DIM; c += 256) {
        float sq = 0.f, sk = 0.f;
#pragma unroll 8
        for (int pix = 0; pix < W2; pix++) {
            sq += qb[(size_t)pix * C_DIM + c];
            sk += kb[(size_t)pix * 1024  + c];
        }
        g_qwin[(size_t)np * C_DIM + c] = sq * (1.f / 64.f);
        g_kwin[(size_t)np * C_DIM + c] = sk * (1.f / 64.f);
    }
}

// ===========================================================================
// Kernel 3: routing logits + top-4 set. grid 784, block 64.
// ===========================================================================
__global__ __launch_bounds__(64) void k3_route() {
    __shared__ float qs[512];
    __shared__ float lg[P2];
    const int np = blockIdx.x;
    const int n  = np / P2;
    const int t  = threadIdx.x;
    for (int c = t; c < 512; c += 64)
        qs[c] = g_qwin[(size_t)np * 512 + c] * SCALE;
    __syncthreads();
    if (t < P2) {
        const float4* kr = (const float4*)(g_kwin + (size_t)(n * P2 + t) * 512);
        float s = 0.f;
#pragma unroll 4
        for (int c4 = 0; c4 < 128; c4++) {
            float4 k4 = kr[c4];
            s += qs[c4 * 4 + 0] * k4.x + qs[c4 * 4 + 1] * k4.y +
                 qs[c4 * 4 + 2] * k4.z + qs[c4 * 4 + 3] * k4.w;
        }
        lg[t] = s;
    }
    __syncthreads();
    if (t == 0) {
        unsigned long long used = 0;
        for (int sel = 0; sel < TOPK; sel++) {
            float best = -1e30f; int bi = 0;
            for (int m = 0; m < P2; m++) {
                if ((used >> m) & 1ULL) continue;
                if (lg[m] > best) { best = lg[m]; bi = m; }
            }
            used |= 1ULL << bi;
            g_idx[np * TOPK + sel] = bi;
        }
    }
}

// ===========================================================================
// Kernel 4: attention, fp16 mma + cp.async + ldmatrix. Block per (head, np).
// Q/K/V smem [64][72 halves] pitch 144B. P-frags direct from softmax regs.
// ===========================================================================
#define K4_TILE 9216                   // 64 * 144
#define K4_SMEM (3 * K4_TILE)          // 27648

__global__ __launch_bounds__(128) void k4_attn_tc() {
    extern __shared__ char smc[];
    const uint32_t sb = smem_u32(smc);
    const uint32_t Qb = sb, Kb = sb + K4_TILE, Vb = sb + 2 * K4_TILE;

    const int head = blockIdx.x;
    const int np   = blockIdx.y;
    const int n    = np / P2;
    const int t    = threadIdx.x;
    const int wid  = t >> 5;
    const int lane = t & 31;
    const int mw   = wid * 16;
    const int lr   = lane >> 2;
    const int lq   = lane & 3;
    const int grp  = lane >> 3, li = lane & 7;

    // fragment address pieces
    const int q_r   = mw + li + ((grp & 1) ? 8 : 0);
    const int q_k   = (grp & 2) ? 8 : 0;
    const int k_n   = li + ((grp & 2) ? 8 : 0);
    const int k_k   = (grp & 1) ? 8 : 0;
    const int v_key = li + ((grp & 1) ? 8 : 0);
    const int v_d   = (grp & 2) ? 8 : 0;

    // ---- Q cp.async (pre-scaled fp16) ----
    const __half* qsrc = g_qh + (size_t)np * 64 * 512 + head * HD;
#pragma unroll
    for (int i = 0; i < 4; i++) {
        int cq = i * 128 + t;
        int pix = cq >> 3, h8 = (cq & 7) * 8;
        CP_ASYNC16(Qb + pix * 144 + h8 * 2, qsrc + (size_t)pix * 512 + h8);
    }
    CP_COMMIT();

    float Of[8][4];
#pragma unroll
    for (int dt = 0; dt < 8; dt++)
#pragma unroll
        for (int i = 0; i < 4; i++) Of[dt][i] = 0.f;
    float mrun0 = -1e30f, mrun1 = -1e30f, lrun0 = 0.f, lrun1 = 0.f;

    for (int tsel = 0; tsel < TOPK; tsel++) {
        const int widx = g_idx[np * TOPK + tsel];
        const __half* kvsrc = g_kvh + (size_t)(n * P2 + widx) * 64 * 1024 + head * HD;
        __syncthreads();                   // prior window's smem reads done
#pragma unroll
        for (int i = 0; i < 4; i++) {
            int cq = i * 128 + t;
            int pix = cq >> 3, h8 = (cq & 7) * 8;
            CP_ASYNC16(Kb + pix * 144 + h8 * 2, kvsrc + (size_t)pix * 1024 + h8);
            CP_ASYNC16(Vb + pix * 144 + h8 * 2, kvsrc + (size_t)pix * 1024 + 512 + h8);
        }
        CP_COMMIT();
        CP_WAIT(0);
        __syncthreads();

        // ---- S = Q.K^T ----
        float sf[8][4];
#pragma unroll
        for (int nt = 0; nt < 8; nt++)
#pragma unroll
            for (int i = 0; i < 4; i++) sf[nt][i] = 0.f;
#pragma unroll
        for (int ks = 0; ks < 4; ks++) {
            uint32_t a[4];
            LDSM_X4(a, Qb + q_r * 144 + (ks * 16 + q_k) * 2);
#pragma unroll
            for (int ntp = 0; ntp < 4; ntp++) {
                uint32_t b[4];
                LDSM_X4(b, Kb + (ntp * 16 + k_n) * 144 + (ks * 16 + k_k) * 2);
                mma_f16(sf[2 * ntp],     a, b[0], b[1]);
                mma_f16(sf[2 * ntp + 1], a, b[2], b[3]);
            }
        }

        // ---- online softmax (rows lr / lr+8) ----
        float mx0 = -1e30f, mx1 = -1e30f;
#pragma unroll
        for (int nt = 0; nt < 8; nt++) {
            mx0 = fmaxf(mx0, fmaxf(sf[nt][0], sf[nt][1]));
            mx1 = fmaxf(mx1, fmaxf(sf[nt][2], sf[nt][3]));
        }
        mx0 = fmaxf(mx0, __shfl_xor_sync(0xffffffffu, mx0, 1));
        mx0 = fmaxf(mx0, __shfl_xor_sync(0xffffffffu, mx0, 2));
        mx1 = fmaxf(mx1, __shfl_xor_sync(0xffffffffu, mx1, 1));
        mx1 = fmaxf(mx1, __shfl_xor_sync(0xffffffffu, mx1, 2));
        const float mn0 = fmaxf(mrun0, mx0);
        const float mn1 = fmaxf(mrun1, mx1);
        const float cor0 = __expf(mrun0 - mn0);
        const float cor1 = __expf(mrun1 - mn1);
        float ls0 = 0.f, ls1 = 0.f;
        uint32_t pf0[8], pf1[8];
#pragma unroll
        for (int nt = 0; nt < 8; nt++) {
            __half2 h0 = __floats2half2_rn(__expf(sf[nt][0] - mn0), __expf(sf[nt][1] - mn0));
            __half2 h1 = __floats2half2_rn(__expf(sf[nt][2] - mn1), __expf(sf[nt][3] - mn1));
            float2 f0 = __half22float2(h0);
            float2 f1 = __half22float2(h1);
            ls0 += f0.x + f0.y;
            ls1 += f1.x + f1.y;
            pf0[nt] = *reinterpret_cast<uint32_t*>(&h0);
            pf1[nt] = *reinterpret_cast<uint32_t*>(&h1);
        }
        ls0 += __shfl_xor_sync(0xffffffffu, ls0, 1);
        ls0 += __shfl_xor_sync(0xffffffffu, ls0, 2);
        ls1 += __shfl_xor_sync(0xffffffffu, ls1, 1);
        ls1 += __shfl_xor_sync(0xffffffffu, ls1, 2);
        lrun0 = lrun0 * cor0 + ls0;
        lrun1 = lrun1 * cor1 + ls1;
        mrun0 = mn0; mrun1 = mn1;
#pragma unroll
        for (int dt = 0; dt < 8; dt++) {
            Of[dt][0] *= cor0; Of[dt][1] *= cor0;
            Of[dt][2] *= cor1; Of[dt][3] *= cor1;
        }

        // ---- O += P.V  (P-fragments straight from registers) ----
#pragma unroll
        for (int ks = 0; ks < 4; ks++) {
            uint32_t a[4] = {pf0[2 * ks], pf1[2 * ks], pf0[2 * ks + 1], pf1[2 * ks + 1]};
#pragma unroll
            for (int dtp = 0; dtp < 4; dtp++) {
                uint32_t b[4];
                LDSM_X4T(b, Vb + (ks * 16 + v_key) * 144 + (dtp * 16 + v_d) * 2);
                mma_f16(Of[2 * dtp],     a, b[0], b[1]);
                mma_f16(Of[2 * dtp + 1], a, b[2], b[3]);
            }
        }
    }

    // ---- write O ----
    const float inv0 = 1.f / lrun0;
    const float inv1 = 1.f / lrun1;
    const size_t obase = (size_t)np * W2 * C_DIM + head * HD;
    float* d0 = g_ao + obase + (size_t)(mw + lr)     * C_DIM;
    float* d1 = g_ao + obase + (size_t)(mw + lr + 8) * C_DIM;
#pragma unroll
    for (int dt = 0; dt < 8; dt++) {
        const int col = dt * 8 + lq * 2;
        *(float2*)(d0 + col) = make_float2(Of[dt][0] * inv0, Of[dt][1] * inv0);
        *(float2*)(d1 + col) = make_float2(Of[dt][2] * inv1, Of[dt][3] * inv1);
    }
}

// ===========================================================================
// Kernel 5: LePE depthwise 3x3 + attn out, NCHW transpose.
// ===========================================================================
__global__ __launch_bounds__(256) void k5_out(const float* __restrict__ wlepe,
                                              const float* __restrict__ blepe,
                                              float* __restrict__ out) {
    __shared__ float stage[64 * 36];
    const int cb = blockIdx.x;
    const int p  = blockIdx.y;
    const int n  = blockIdx.z;
    const int c0 = cb * 32;
    const int t  = threadIdx.x;
    const int c  = t & 31;
    const int pr = t >> 5;

    float wl[9];
#pragma unroll
    for (int k = 0; k < 9; k++) wl[k] = wlepe[(c0 + c) * 9 + k];
    const float bias = blepe[c0 + c];

    const int wh0 = (p / NWIN) * 8;
    const int ww0 = (p % NWIN) * 8;

    for (int pg = 0; pg < 8; pg++) {
        int pix = pg * 8 + pr;
        int ih = pix >> 3, iw = pix & 7;
        int h = wh0 + ih, w = ww0 + iw;
        float acc = bias;
#pragma unroll
        for (int kh = 0; kh < 3; kh++) {
            int hh = h + kh - 1;
            if (hh < 0 || hh >= H_IMG) continue;
#pragma unroll
            for (int kw = 0; kw < 3; kw++) {
                int ww = w + kw - 1;
                if (ww < 0 || ww >= W_IMG) continue;
                int pp   = (hh >> 3) * NWIN + (ww >> 3);
                int ppix = ((hh & 7) << 3) + (ww & 7);
                float vv = g_kv[((size_t)(n * P2 + pp) * W2 + ppix) * 1024 + 512 + c0 + c];
                acc += vv * wl[kh * 3 + kw];
            }
        }
        acc += g_ao[((size_t)(n * P2 + p) * W2 + pix) * C_DIM + c0 + c];
        stage[pix * 36 + c] = acc;
    }
    __syncthreads();

    const int wc = t >> 3;
    const int wx = t & 7;
    const size_t obase = ((size_t)n * C_DIM + c0 + wc) * HW;
    for (int h = 0; h < 8; h++) {
        out[obase + (size_t)(wh0 + h) * W_IMG + ww0 + wx] = stage[(h * 8 + wx) * 36 + wc];
    }
}

// ===========================================================================
extern "C" void kernel_launch(void* const* d_in, const int* in_sizes, int n_in,
                              void* d_out, int out_size) {
    const float* x      = (const float*)d_in[0];
    const float* w_qkv  = (const float*)d_in[1];
    const float* b_qkv  = (const float*)d_in[2];
    const float* w_lepe = (const float*)d_in[3];
    const float* b_lepe = (const float*)d_in[4];
    float* out = (float*)d_out;

    cudaFuncSetAttribute(k1_qkv_tc, cudaFuncAttributeMaxDynamicSharedMemorySize, K1_SMEM);
    cudaFuncSetAttribute(k4_attn_tc, cudaFuncAttributeMaxDynamicSharedMemorySize, K4_SMEM);

    k0_half<<<25088, 256>>>(x, w_qkv);
    k1_qkv_tc<<<dim3(12, 392), 256, K1_SMEM>>>(b_qkv);
    k2_mean<<<784, 256>>>();
    k3_route<<<784, 64>>>();
    k4_attn_tc<<<dim3(HEADS, N_IMG * P2), 128, K4_SMEM>>>();
    k5_out<<<dim3(16, P2, N_IMG), 256>>>(w_lepe, b_lepe, out);
}

// round 8
// speedup vs baseline: 7.8347x; 1.0192x over previous
#include <cuda_runtime.h>
#include <cuda_fp16.h>
#include <cstdint>

// ---------------------------------------------------------------------------
// DeBiLevelRoutingAttention block. Round 8: all-fp16 data plane.
// fp32 g_q/g_kv/g_ao eliminated; routing means from fp16 with fp32 accum;
// k4 double-buffered cp.async over the 4 selected windows.
// ---------------------------------------------------------------------------

#define N_IMG  16
#define C_DIM  512
#define H_IMG  56
#define W_IMG  56
#define HW     3136
#define CHW    (C_DIM * HW)
#define QKC    512
#define NWIN   7
#define P2     49
#define W2     64
#define TOPK   4
#define HEADS  8
#define HD     64
#define SCALE  0.04419417382415922f   // 512^-0.5

// ----------------------------- scratch ------------------------------------
__device__ float g_qwin[(size_t)N_IMG * P2 * C_DIM];
__device__ float g_kwin[(size_t)N_IMG * P2 * C_DIM];
__device__ int   g_idx [N_IMG * P2 * TOPK];
__device__ __align__(16) __half g_xh [(size_t)N_IMG * CHW];
__device__ __align__(16) __half g_wh [1536 * 512];
__device__ __align__(16) __half g_qh [(size_t)N_IMG * P2 * W2 * 512];   // pre-scaled
__device__ __align__(16) __half g_kvh[(size_t)N_IMG * P2 * W2 * 1024];
__device__ __align__(16) __half g_aoh[(size_t)N_IMG * P2 * W2 * 512];

// ----------------------------- helpers ------------------------------------
__device__ __forceinline__ uint32_t pack2(float lo, float hi) {
    __half2 h = __floats2half2_rn(lo, hi);
    return *reinterpret_cast<uint32_t*>(&h);
}
__device__ __forceinline__ uint32_t smem_u32(const void* p) {
    return (uint32_t)__cvta_generic_to_shared(p);
}
__device__ __forceinline__ void mma_f16(float c[4], const uint32_t a[4],
                                        uint32_t b0, uint32_t b1) {
    asm volatile(
        "mma.sync.aligned.m16n8k16.row.col.f32.f16.f16.f32 "
        "{%0,%1,%2,%3}, {%4,%5,%6,%7}, {%8,%9}, {%0,%1,%2,%3};"
        : "+f"(c[0]), "+f"(c[1]), "+f"(c[2]), "+f"(c[3])
        : "r"(a[0]), "r"(a[1]), "r"(a[2]), "r"(a[3]), "r"(b0), "r"(b1));
}
#define CP_ASYNC16(dst, src) \
    asm volatile("cp.async.cg.shared.global [%0], [%1], 16;" \
                 :: "r"(dst), "l"(src) : "memory")
#define CP_COMMIT() asm volatile("cp.async.commit_group;" ::: "memory")
#define CP_WAIT(n)  asm volatile("cp.async.wait_group %0;" :: "n"(n) : "memory")
#define LDSM_X4(r, a) \
    asm volatile("ldmatrix.sync.aligned.m8n8.x4.shared.b16 {%0,%1,%2,%3}, [%4];" \
        : "=r"((r)[0]), "=r"((r)[1]), "=r"((r)[2]), "=r"((r)[3]) : "r"(a))
#define LDSM_X4T(r, a) \
    asm volatile("ldmatrix.sync.aligned.m8n8.x4.trans.shared.b16 {%0,%1,%2,%3}, [%4];" \
        : "=r"((r)[0]), "=r"((r)[1]), "=r"((r)[2]), "=r"((r)[3]) : "r"(a))

// ===========================================================================
// Kernel 0: convert x and w_qkv to fp16.
// ===========================================================================
__global__ __launch_bounds__(256) void k0_half(const float* __restrict__ x,
                                               const float* __restrict__ w) {
    const int i = blockIdx.x * 256 + threadIdx.x;
    const int NX4 = (N_IMG * CHW) >> 2;
    const int NW4 = (1536 * 512) >> 2;
    if (i < NX4) {
        float4 v = ((const float4*)x)[i];
        uint32_t* d = (uint32_t*)g_xh;
        d[2 * i]     = pack2(v.x, v.y);
        d[2 * i + 1] = pack2(v.z, v.w);
    }
    if (i < NW4) {
        float4 v = ((const float4*)w)[i];
        uint32_t* d = (uint32_t*)g_wh;
        d[2 * i]     = pack2(v.x, v.y);
        d[2 * i + 1] = pack2(v.z, v.w);
    }
}

// ===========================================================================
// Kernel 1: QKV GEMM, fp16 mma + cp.async 4-stage + ldmatrix.
// Epilogue: bias + window scatter, fp16 only (q pre-scaled by SCALE).
// ===========================================================================
#define K1_ABYTES 8704                 // 32 * 272
#define K1_BBYTES 10240                // 128 * 80
#define K1_STAGE  (K1_ABYTES + K1_BBYTES)
#define K1_SMEM   (4 * K1_STAGE)

__global__ __launch_bounds__(256) void k1_qkv_tc(const float* __restrict__ bqkv) {
    extern __shared__ char smc[];
    const uint32_t sb = smem_u32(smc);
    const int t  = threadIdx.x;
    const int o0 = blockIdx.x * 128;
    const int m0 = blockIdx.y * 128;

    const int m16h = (t & 15) * 8;
    const int kr0  = t >> 4;
    const int mA   = m0 + m16h;
    const int nA   = mA / HW;
    const int hwA  = mA - nA * HW;
    const __half* axp = g_xh + (size_t)nA * CHW + hwA;
    const int bn0 = t >> 2;
    const int bk8 = (t & 3) * 8;
    const __half* bw0 = g_wh + (size_t)(o0 + bn0) * 512 + bk8;

    const int wid = t >> 5, lane = t & 31;
    const int mw = (wid & 3) * 32;
    const int nw = (wid >> 2) * 64;
    const int grp = lane >> 3, li = lane & 7;
    const int a_k = li + ((grp & 2) ? 8 : 0);
    const int a_m = (grp & 1) ? 8 : 0;
    const int b_n = li + ((grp & 2) ? 8 : 0);
    const int b_k = (grp & 1) ? 8 : 0;
    const int lr = lane >> 2, lq = lane & 3;

    float c[2][8][4];
#pragma unroll
    for (int mt = 0; mt < 2; mt++)
#pragma unroll
        for (int nt = 0; nt < 8; nt++)
#pragma unroll
            for (int i = 0; i < 4; i++) c[mt][nt][i] = 0.f;

#define K1_ISSUE(kc_) do {                                                    \
    const int s_ = (kc_) & 3;                                                 \
    const uint32_t ab_ = sb + s_ * K1_STAGE;                                  \
    const uint32_t bb_ = ab_ + K1_ABYTES;                                     \
    CP_ASYNC16(ab_ + kr0 * 272 + m16h * 2,                                    \
               axp + (size_t)((kc_) * 32 + kr0) * HW);                        \
    CP_ASYNC16(ab_ + (16 + kr0) * 272 + m16h * 2,                             \
               axp + (size_t)((kc_) * 32 + 16 + kr0) * HW);                   \
    CP_ASYNC16(bb_ + bn0 * 80 + bk8 * 2, bw0 + (kc_) * 32);                   \
    CP_ASYNC16(bb_ + (64 + bn0) * 80 + bk8 * 2,                               \
               bw0 + 64 * 512 + (kc_) * 32);                                  \
} while (0)

    K1_ISSUE(0); CP_COMMIT();
    K1_ISSUE(1); CP_COMMIT();
    K1_ISSUE(2); CP_COMMIT();

    for (int kc = 0; kc < 16; kc++) {
        CP_WAIT(2);
        __syncthreads();
        if (kc + 3 < 16) { K1_ISSUE(kc + 3); }
        CP_COMMIT();
        const uint32_t ab = sb + (kc & 3) * K1_STAGE;
        const uint32_t bb = ab + K1_ABYTES;
#pragma unroll
        for (int ks = 0; ks < 2; ks++) {
            uint32_t a[2][4];
#pragma unroll
            for (int mt = 0; mt < 2; mt++)
                LDSM_X4T(a[mt], ab + (ks * 16 + a_k) * 272 + (mw + mt * 16 + a_m) * 2);
            uint32_t b[4][4];
#pragma unroll
            for (int ntp = 0; ntp < 4; ntp++)
                LDSM_X4(b[ntp], bb + (nw + ntp * 16 + b_n) * 80 + (ks * 16 + b_k) * 2);
#pragma unroll
            for (int ntp = 0; ntp < 4; ntp++) {
                mma_f16(c[0][2 * ntp],     a[0], b[ntp][0], b[ntp][1]);
                mma_f16(c[0][2 * ntp + 1], a[0], b[ntp][2], b[ntp][3]);
                mma_f16(c[1][2 * ntp],     a[1], b[ntp][0], b[ntp][1]);
                mma_f16(c[1][2 * ntp + 1], a[1], b[ntp][2], b[ntp][3]);
            }
        }
    }

    const bool isq = (o0 < QKC);
#pragma unroll
    for (int mt = 0; mt < 2; mt++) {
#pragma unroll
        for (int half = 0; half < 2; half++) {
            const int row = mw + mt * 16 + lr + half * 8;
            const int m   = m0 + row;
            const int n   = m / HW;
            const int hw  = m - n * HW;
            const int h   = hw / W_IMG;
            const int wp  = hw - h * W_IMG;
            const int p   = (h >> 3) * NWIN + (wp >> 3);
            const int pix = ((h & 7) << 3) + (wp & 7);
            const size_t npix = (size_t)((n * P2 + p) * W2 + pix);
            uint32_t* dsth = isq ? ((uint32_t*)g_qh  + npix * 256 + (o0 >> 1))
                                 : ((uint32_t*)g_kvh + npix * 512 + ((o0 - QKC) >> 1));
#pragma unroll
            for (int nt = 0; nt < 8; nt++) {
                const int col = nw + nt * 8 + lq * 2;
                float vx = c[mt][nt][half * 2 + 0] + bqkv[o0 + col];
                float vy = c[mt][nt][half * 2 + 1] + bqkv[o0 + col + 1];
                dsth[col >> 1] = isq ? pack2(vx * SCALE, vy * SCALE) : pack2(vx, vy);
            }
        }
    }
#undef K1_ISSUE
}

// ===========================================================================
// Kernel 2: window means from fp16 q/kv, fp32 accumulation. grid 784 x 256.
// Each thread owns one half2 column (2 channels).
// ===========================================================================
__global__ __launch_bounds__(256) void k2_mean() {
    const int np = blockIdx.x;
    const int c2 = threadIdx.x;               // 0..255
    const uint32_t* qb = (const uint32_t*)g_qh  + (size_t)np * W2 * 256 + c2;
    const uint32_t* kb = (const uint32_t*)g_kvh + (size_t)np * W2 * 512 + c2;
    float sqx = 0.f, sqy = 0.f, skx = 0.f, sky = 0.f;
#pragma unroll 8
    for (int pix = 0; pix < W2; pix++) {
        uint32_t qv = qb[(size_t)pix * 256];
        uint32_t kv = kb[(size_t)pix * 512];
        float2 qf = __half22float2(*reinterpret_cast<__half2*>(&qv));
        float2 kf = __half22float2(*reinterpret_cast<__half2*>(&kv));
        sqx += qf.x; sqy += qf.y;
        skx += kf.x; sky += kf.y;
    }
    // q means are pre-scaled by SCALE (folded into g_qh)
    *(float2*)(g_qwin + (size_t)np * 512 + 2 * c2) = make_float2(sqx * (1.f/64.f), sqy * (1.f/64.f));
    *(float2*)(g_kwin + (size_t)np * 512 + 2 * c2) = make_float2(skx * (1.f/64.f), sky * (1.f/64.f));
}

// ===========================================================================
// Kernel 3: routing logits + top-4 set. grid 784, block 128 (2 thr/window).
// q_win already carries SCALE.
// ===========================================================================
__global__ __launch_bounds__(128) void k3_route() {
    __shared__ float qs[512];
    __shared__ float lg[P2];
    const int np = blockIdx.x;
    const int n  = np / P2;
    const int t  = threadIdx.x;
    for (int c = t; c < 512; c += 128)
        qs[c] = g_qwin[(size_t)np * 512 + c];
    __syncthreads();
    {
        const int win  = (t >> 1) < P2 ? (t >> 1) : (P2 - 1);
        const int hf   = t & 1;
        const float4* kr = (const float4*)(g_kwin + (size_t)(n * P2 + win) * 512) + hf * 64;
        const float*  qh = qs + hf * 256;
        float s = 0.f;
#pragma unroll 8
        for (int c4 = 0; c4 < 64; c4++) {
            float4 k4 = kr[c4];
            s += qh[c4 * 4 + 0] * k4.x + qh[c4 * 4 + 1] * k4.y +
                 qh[c4 * 4 + 2] * k4.z + qh[c4 * 4 + 3] * k4.w;
        }
        s += __shfl_xor_sync(0xffffffffu, s, 1);
        if (hf == 0 && (t >> 1) < P2) lg[win] = s;
    }
    __syncthreads();
    if (t == 0) {
        unsigned long long used = 0;
        for (int sel = 0; sel < TOPK; sel++) {
            float best = -1e30f; int bi = 0;
            for (int m = 0; m < P2; m++) {
                if ((used >> m) & 1ULL) continue;
                if (lg[m] > best) { best = lg[m]; bi = m; }
            }
            used |= 1ULL << bi;
            g_idx[np * TOPK + sel] = bi;
        }
    }
}

// ===========================================================================
// Kernel 4: attention, fp16 mma + double-buffered cp.async KV + ldmatrix.
// smem: Q + 2x(K,V) tiles of 64x72 halves pitch 144B. P-frags from registers.
// ===========================================================================
#define K4_TILE 9216                   // 64 * 144
#define K4_SMEM (5 * K4_TILE)          // Q + K0 V0 K1 V1 = 46080

__global__ __launch_bounds__(128) void k4_attn_tc() {
    extern __shared__ char smc[];
    const uint32_t sb = smem_u32(smc);
    const uint32_t Qb = sb;

    const int head = blockIdx.x;
    const int np   = blockIdx.y;
    const int n    = np / P2;
    const int t    = threadIdx.x;
    const int wid  = t >> 5;
    const int lane = t & 31;
    const int mw   = wid * 16;
    const int lr   = lane >> 2;
    const int lq   = lane & 3;
    const int grp  = lane >> 3, li = lane & 7;

    const int q_r   = mw + li + ((grp & 1) ? 8 : 0);
    const int q_k   = (grp & 2) ? 8 : 0;
    const int k_n   = li + ((grp & 2) ? 8 : 0);
    const int k_k   = (grp & 1) ? 8 : 0;
    const int v_key = li + ((grp & 1) ? 8 : 0);
    const int v_d   = (grp & 2) ? 8 : 0;

    int widx[TOPK];
#pragma unroll
    for (int i = 0; i < TOPK; i++) widx[i] = g_idx[np * TOPK + i];

    const int pixL = t >> 1;                    // 0..63
    const int h8L  = (t & 1) * 32;              // two 16B chunks per thread per tile? no:
    // loader: 128 threads x 4 iterations cover 64 pix x 64 halves (8 chunks of 8)
#define K4_KV_ISSUE(ts_) do {                                                   \
    const int s_ = (ts_) & 1;                                                   \
    const uint32_t Kb_ = sb + (1 + 2 * s_) * K4_TILE;                           \
    const uint32_t Vb_ = Kb_ + K4_TILE;                                         \
    const __half* kvsrc_ = g_kvh + (size_t)(n * P2 + widx[ts_]) * 64 * 1024 + head * HD; \
    _Pragma("unroll")                                                           \
    for (int i_ = 0; i_ < 4; i_++) {                                            \
        int cq_ = i_ * 128 + t;                                                 \
        int pix_ = cq_ >> 3, h8_ = (cq_ & 7) * 8;                               \
        CP_ASYNC16(Kb_ + pix_ * 144 + h8_ * 2, kvsrc_ + (size_t)pix_ * 1024 + h8_);       \
        CP_ASYNC16(Vb_ + pix_ * 144 + h8_ * 2, kvsrc_ + (size_t)pix_ * 1024 + 512 + h8_); \
    }                                                                           \
} while (0)

    // G0: Q + window 0; G1: window 1
    {
        const __half* qsrc = g_qh + (size_t)np * 64 * 512 + head * HD;
#pragma unroll
        for (int i = 0; i < 4; i++) {
            int cq = i * 128 + t;
            int pix = cq >> 3, h8 = (cq & 7) * 8;
            CP_ASYNC16(Qb + pix * 144 + h8 * 2, qsrc + (size_t)pix * 512 + h8);
        }
        K4_KV_ISSUE(0);
        CP_COMMIT();
        K4_KV_ISSUE(1);
        CP_COMMIT();
    }
    (void)pixL; (void)h8L;

    float Of[8][4];
#pragma unroll
    for (int dt = 0; dt < 8; dt++)
#pragma unroll
        for (int i = 0; i < 4; i++) Of[dt][i] = 0.f;
    float mrun0 = -1e30f, mrun1 = -1e30f, lrun0 = 0.f, lrun1 = 0.f;

    for (int tsel = 0; tsel < TOPK; tsel++) {
        CP_WAIT(1);
        __syncthreads();
        const uint32_t Kb = sb + (1 + 2 * (tsel & 1)) * K4_TILE;
        const uint32_t Vb = Kb + K4_TILE;

        // ---- S = Q.K^T ----
        float sf[8][4];
#pragma unroll
        for (int nt = 0; nt < 8; nt++)
#pragma unroll
            for (int i = 0; i < 4; i++) sf[nt][i] = 0.f;
#pragma unroll
        for (int ks = 0; ks < 4; ks++) {
            uint32_t a[4];
            LDSM_X4(a, Qb + q_r * 144 + (ks * 16 + q_k) * 2);
#pragma unroll
            for (int ntp = 0; ntp < 4; ntp++) {
                uint32_t b[4];
                LDSM_X4(b, Kb + (ntp * 16 + k_n) * 144 + (ks * 16 + k_k) * 2);
                mma_f16(sf[2 * ntp],     a, b[0], b[1]);
                mma_f16(sf[2 * ntp + 1], a, b[2], b[3]);
            }
        }

        // ---- online softmax ----
        float mx0 = -1e30f, mx1 = -1e30f;
#pragma unroll
        for (int nt = 0; nt < 8; nt++) {
            mx0 = fmaxf(mx0, fmaxf(sf[nt][0], sf[nt][1]));
            mx1 = fmaxf(mx1, fmaxf(sf[nt][2], sf[nt][3]));
        }
        mx0 = fmaxf(mx0, __shfl_xor_sync(0xffffffffu, mx0, 1));
        mx0 = fmaxf(mx0, __shfl_xor_sync(0xffffffffu, mx0, 2));
        mx1 = fmaxf(mx1, __shfl_xor_sync(0xffffffffu, mx1, 1));
        mx1 = fmaxf(mx1, __shfl_xor_sync(0xffffffffu, mx1, 2));
        const float mn0 = fmaxf(mrun0, mx0);
        const float mn1 = fmaxf(mrun1, mx1);
        const float cor0 = __expf(mrun0 - mn0);
        const float cor1 = __expf(mrun1 - mn1);
        float ls0 = 0.f, ls1 = 0.f;
        uint32_t pf0[8], pf1[8];
#pragma unroll
        for (int nt = 0; nt < 8; nt++) {
            __half2 h0 = __floats2half2_rn(__expf(sf[nt][0] - mn0), __expf(sf[nt][1] - mn0));
            __half2 h1 = __floats2half2_rn(__expf(sf[nt][2] - mn1), __expf(sf[nt][3] - mn1));
            float2 f0 = __half22float2(h0);
            float2 f1 = __half22float2(h1);
            ls0 += f0.x + f0.y;
            ls1 += f1.x + f1.y;
            pf0[nt] = *reinterpret_cast<uint32_t*>(&h0);
            pf1[nt] = *reinterpret_cast<uint32_t*>(&h1);
        }
        ls0 += __shfl_xor_sync(0xffffffffu, ls0, 1);
        ls0 += __shfl_xor_sync(0xffffffffu, ls0, 2);
        ls1 += __shfl_xor_sync(0xffffffffu, ls1, 1);
        ls1 += __shfl_xor_sync(0xffffffffu, ls1, 2);
        lrun0 = lrun0 * cor0 + ls0;
        lrun1 = lrun1 * cor1 + ls1;
        mrun0 = mn0; mrun1 = mn1;
#pragma unroll
        for (int dt = 0; dt < 8; dt++) {
            Of[dt][0] *= cor0; Of[dt][1] *= cor0;
            Of[dt][2] *= cor1; Of[dt][3] *= cor1;
        }

        // ---- O += P.V ----
#pragma unroll
        for (int ks = 0; ks < 4; ks++) {
            uint32_t a[4] = {pf0[2 * ks], pf1[2 * ks], pf0[2 * ks + 1], pf1[2 * ks + 1]};
#pragma unroll
            for (int dtp = 0; dtp < 4; dtp++) {
                uint32_t b[4];
                LDSM_X4T(b, Vb + (ks * 16 + v_key) * 144 + (dtp * 16 + v_d) * 2);
                mma_f16(Of[2 * dtp],     a, b[0], b[1]);
                mma_f16(Of[2 * dtp + 1], a, b[2], b[3]);
            }
        }

        __syncthreads();                       // smem reads done before re-issue
        if (tsel + 2 < TOPK) { K4_KV_ISSUE(tsel + 2); }
        CP_COMMIT();
    }

    // ---- write O (fp16) ----
    const float inv0 = 1.f / lrun0;
    const float inv1 = 1.f / lrun1;
    uint32_t* d0 = (uint32_t*)g_aoh + ((size_t)np * W2 + mw + lr)     * 256 + head * 32;
    uint32_t* d1 = (uint32_t*)g_aoh + ((size_t)np * W2 + mw + lr + 8) * 256 + head * 32;
#pragma unroll
    for (int dt = 0; dt < 8; dt++) {
        d0[dt * 4 + lq] = pack2(Of[dt][0] * inv0, Of[dt][1] * inv0);
        d1[dt * 4 + lq] = pack2(Of[dt][2] * inv1, Of[dt][3] * inv1);
    }
#undef K4_KV_ISSUE
}

// ===========================================================================
// Kernel 5: LePE depthwise 3x3 on fp16 v + fp16 attn out, NCHW fp32 output.
// ===========================================================================
__global__ __launch_bounds__(256) void k5_out(const float* __restrict__ wlepe,
                                              const float* __restrict__ blepe,
                                              float* __restrict__ out) {
    __shared__ float stage[64 * 36];
    const int cb = blockIdx.x;
    const int p  = blockIdx.y;
    const int n  = blockIdx.z;
    const int c0 = cb * 32;
    const int t  = threadIdx.x;
    const int c  = t & 31;
    const int pr = t >> 5;

    float wl[9];
#pragma unroll
    for (int k = 0; k < 9; k++) wl[k] = wlepe[(c0 + c) * 9 + k];
    const float bias = blepe[c0 + c];

    const int wh0 = (p / NWIN) * 8;
    const int ww0 = (p % NWIN) * 8;

    for (int pg = 0; pg < 8; pg++) {
        int pix = pg * 8 + pr;
        int ih = pix >> 3, iw = pix & 7;
        int h = wh0 + ih, w = ww0 + iw;
        float acc = bias;
#pragma unroll
        for (int kh = 0; kh < 3; kh++) {
            int hh = h + kh - 1;
            if (hh < 0 || hh >= H_IMG) continue;
#pragma unroll
            for (int kw = 0; kw < 3; kw++) {
                int ww = w + kw - 1;
                if (ww < 0 || ww >= W_IMG) continue;
                int pp   = (hh >> 3) * NWIN + (ww >> 3);
                int ppix = ((hh & 7) << 3) + (ww & 7);
                float vv = __half2float(
                    g_kvh[((size_t)(n * P2 + pp) * W2 + ppix) * 1024 + 512 + c0 + c]);
                acc += vv * wl[kh * 3 + kw];
            }
        }
        acc += __half2float(g_aoh[((size_t)(n * P2 + p) * W2 + pix) * 512 + c0 + c]);
        stage[pix * 36 + c] = acc;
    }
    __syncthreads();

    const int wc = t >> 3;
    const int wx = t & 7;
    const size_t obase = ((size_t)n * C_DIM + c0 + wc) * HW;
    for (int h = 0; h < 8; h++) {
        out[obase + (size_t)(wh0 + h) * W_IMG + ww0 + wx] = stage[(h * 8 + wx) * 36 + wc];
    }
}

// ===========================================================================
extern "C" void kernel_launch(void* const* d_in, const int* in_sizes, int n_in,
                              void* d_out, int out_size) {
    const float* x      = (const float*)d_in[0];
    const float* w_qkv  = (const float*)d_in[1];
    const float* b_qkv  = (const float*)d_in[2];
    const float* w_lepe = (const float*)d_in[3];
    const float* b_lepe = (const float*)d_in[4];
    float* out = (float*)d_out;

    cudaFuncSetAttribute(k1_qkv_tc, cudaFuncAttributeMaxDynamicSharedMemorySize, K1_SMEM);
    cudaFuncSetAttribute(k4_attn_tc, cudaFuncAttributeMaxDynamicSharedMemorySize, K4_SMEM);

    k0_half<<<25088, 256>>>(x, w_qkv);
    k1_qkv_tc<<<dim3(12, 392), 256, K1_SMEM>>>(b_qkv);
    k2_mean<<<784, 256>>>();
    k3_route<<<784, 128>>>();
    k4_attn_tc<<<dim3(HEADS, N_IMG * P2), 128, K4_SMEM>>>();
    k5_out<<<dim3(16, P2, N_IMG), 256>>>(w_lepe, b_lepe, out);
}

// round 10
// speedup vs baseline: 8.0503x; 1.0275x over previous
#include <cuda_runtime.h>
#include <cuda_fp16.h>
#include <cstdint>

// ---------------------------------------------------------------------------
// DeBiLevelRoutingAttention block. Round 10 (= R9 resubmit; infra failure).
// k5 half2, k3 parallel top-k, + two no-op launches so ncu lands on k1.
// ---------------------------------------------------------------------------

#define N_IMG  16
#define C_DIM  512
#define H_IMG  56
#define W_IMG  56
#define HW     3136
#define CHW    (C_DIM * HW)
#define QKC    512
#define NWIN   7
#define P2     49
#define W2     64
#define TOPK   4
#define HEADS  8
#define HD     64
#define SCALE  0.04419417382415922f   // 512^-0.5

// ----------------------------- scratch ------------------------------------
__device__ float g_qwin[(size_t)N_IMG * P2 * C_DIM];
__device__ float g_kwin[(size_t)N_IMG * P2 * C_DIM];
__device__ int   g_idx [N_IMG * P2 * TOPK];
__device__ __align__(16) __half g_xh [(size_t)N_IMG * CHW];
__device__ __align__(16) __half g_wh [1536 * 512];
__device__ __align__(16) __half g_qh [(size_t)N_IMG * P2 * W2 * 512];   // pre-scaled
__device__ __align__(16) __half g_kvh[(size_t)N_IMG * P2 * W2 * 1024];
__device__ __align__(16) __half g_aoh[(size_t)N_IMG * P2 * W2 * 512];

// ----------------------------- helpers ------------------------------------
__device__ __forceinline__ uint32_t pack2(float lo, float hi) {
    __half2 h = __floats2half2_rn(lo, hi);
    return *reinterpret_cast<uint32_t*>(&h);
}
__device__ __forceinline__ uint32_t smem_u32(const void* p) {
    return (uint32_t)__cvta_generic_to_shared(p);
}
__device__ __forceinline__ void mma_f16(float c[4], const uint32_t a[4],
                                        uint32_t b0, uint32_t b1) {
    asm volatile(
        "mma.sync.aligned.m16n8k16.row.col.f32.f16.f16.f32 "
        "{%0,%1,%2,%3}, {%4,%5,%6,%7}, {%8,%9}, {%0,%1,%2,%3};"
        : "+f"(c[0]), "+f"(c[1]), "+f"(c[2]), "+f"(c[3])
        : "r"(a[0]), "r"(a[1]), "r"(a[2]), "r"(a[3]), "r"(b0), "r"(b1));
}
#define CP_ASYNC16(dst, src) \
    asm volatile("cp.async.cg.shared.global [%0], [%1], 16;" \
                 :: "r"(dst), "l"(src) : "memory")
#define CP_COMMIT() asm volatile("cp.async.commit_group;" ::: "memory")
#define CP_WAIT(n)  asm volatile("cp.async.wait_group %0;" :: "n"(n) : "memory")
#define LDSM_X4(r, a) \
    asm volatile("ldmatrix.sync.aligned.m8n8.x4.shared.b16 {%0,%1,%2,%3}, [%4];" \
        : "=r"((r)[0]), "=r"((r)[1]), "=r"((r)[2]), "=r"((r)[3]) : "r"(a))
#define LDSM_X4T(r, a) \
    asm volatile("ldmatrix.sync.aligned.m8n8.x4.trans.shared.b16 {%0,%1,%2,%3}, [%4];" \
        : "=r"((r)[0]), "=r"((r)[1]), "=r"((r)[2]), "=r"((r)[3]) : "r"(a))

// ===========================================================================
// Dummy no-op kernel: shifts ncu's captured launch index onto k1.
// ===========================================================================
__global__ void kd_nop() {}

// ===========================================================================
// Kernel 0: convert x and w_qkv to fp16.
// ===========================================================================
__global__ __launch_bounds__(256) void k0_half(const float* __restrict__ x,
                                               const float* __restrict__ w) {
    const int i = blockIdx.x * 256 + threadIdx.x;
    const int NX4 = (N_IMG * CHW) >> 2;
    const int NW4 = (1536 * 512) >> 2;
    if (i < NX4) {
        float4 v = ((const float4*)x)[i];
        uint32_t* d = (uint32_t*)g_xh;
        d[2 * i]     = pack2(v.x, v.y);
        d[2 * i + 1] = pack2(v.z, v.w);
    }
    if (i < NW4) {
        float4 v = ((const float4*)w)[i];
        uint32_t* d = (uint32_t*)g_wh;
        d[2 * i]     = pack2(v.x, v.y);
        d[2 * i + 1] = pack2(v.z, v.w);
    }
}

// ===========================================================================
// Kernel 1: QKV GEMM, fp16 mma + cp.async 4-stage + ldmatrix (unchanged).
// ===========================================================================
#define K1_ABYTES 8704                 // 32 * 272
#define K1_BBYTES 10240                // 128 * 80
#define K1_STAGE  (K1_ABYTES + K1_BBYTES)
#define K1_SMEM   (4 * K1_STAGE)

__global__ __launch_bounds__(256) void k1_qkv_tc(const float* __restrict__ bqkv) {
    extern __shared__ char smc[];
    const uint32_t sb = smem_u32(smc);
    const int t  = threadIdx.x;
    const int o0 = blockIdx.x * 128;
    const int m0 = blockIdx.y * 128;

    const int m16h = (t & 15) * 8;
    const int kr0  = t >> 4;
    const int mA   = m0 + m16h;
    const int nA   = mA / HW;
    const int hwA  = mA - nA * HW;
    const __half* axp = g_xh + (size_t)nA * CHW + hwA;
    const int bn0 = t >> 2;
    const int bk8 = (t & 3) * 8;
    const __half* bw0 = g_wh + (size_t)(o0 + bn0) * 512 + bk8;

    const int wid = t >> 5, lane = t & 31;
    const int mw = (wid & 3) * 32;
    const int nw = (wid >> 2) * 64;
    const int grp = lane >> 3, li = lane & 7;
    const int a_k = li + ((grp & 2) ? 8 : 0);
    const int a_m = (grp & 1) ? 8 : 0;
    const int b_n = li + ((grp & 2) ? 8 : 0);
    const int b_k = (grp & 1) ? 8 : 0;
    const int lr = lane >> 2, lq = lane & 3;

    float c[2][8][4];
#pragma unroll
    for (int mt = 0; mt < 2; mt++)
#pragma unroll
        for (int nt = 0; nt < 8; nt++)
#pragma unroll
            for (int i = 0; i < 4; i++) c[mt][nt][i] = 0.f;

#define K1_ISSUE(kc_) do {                                                    \
    const int s_ = (kc_) & 3;                                                 \
    const uint32_t ab_ = sb + s_ * K1_STAGE;                                  \
    const uint32_t bb_ = ab_ + K1_ABYTES;                                     \
    CP_ASYNC16(ab_ + kr0 * 272 + m16h * 2,                                    \
               axp + (size_t)((kc_) * 32 + kr0) * HW);                        \
    CP_ASYNC16(ab_ + (16 + kr0) * 272 + m16h * 2,                             \
               axp + (size_t)((kc_) * 32 + 16 + kr0) * HW);                   \
    CP_ASYNC16(bb_ + bn0 * 80 + bk8 * 2, bw0 + (kc_) * 32);                   \
    CP_ASYNC16(bb_ + (64 + bn0) * 80 + bk8 * 2,                               \
               bw0 + 64 * 512 + (kc_) * 32);                                  \
} while (0)

    K1_ISSUE(0); CP_COMMIT();
    K1_ISSUE(1); CP_COMMIT();
    K1_ISSUE(2); CP_COMMIT();

    for (int kc = 0; kc < 16; kc++) {
        CP_WAIT(2);
        __syncthreads();
        if (kc + 3 < 16) { K1_ISSUE(kc + 3); }
        CP_COMMIT();
        const uint32_t ab = sb + (kc & 3) * K1_STAGE;
        const uint32_t bb = ab + K1_ABYTES;
#pragma unroll
        for (int ks = 0; ks < 2; ks++) {
            uint32_t a[2][4];
#pragma unroll
            for (int mt = 0; mt < 2; mt++)
                LDSM_X4T(a[mt], ab + (ks * 16 + a_k) * 272 + (mw + mt * 16 + a_m) * 2);
            uint32_t b[4][4];
#pragma unroll
            for (int ntp = 0; ntp < 4; ntp++)
                LDSM_X4(b[ntp], bb + (nw + ntp * 16 + b_n) * 80 + (ks * 16 + b_k) * 2);
#pragma unroll
            for (int ntp = 0; ntp < 4; ntp++) {
                mma_f16(c[0][2 * ntp],     a[0], b[ntp][0], b[ntp][1]);
                mma_f16(c[0][2 * ntp + 1], a[0], b[ntp][2], b[ntp][3]);
                mma_f16(c[1][2 * ntp],     a[1], b[ntp][0], b[ntp][1]);
                mma_f16(c[1][2 * ntp + 1], a[1], b[ntp][2], b[ntp][3]);
            }
        }
    }

    const bool isq = (o0 < QKC);
#pragma unroll
    for (int mt = 0; mt < 2; mt++) {
#pragma unroll
        for (int half = 0; half < 2; half++) {
            const int row = mw + mt * 16 + lr + half * 8;
            const int m   = m0 + row;
            const int n   = m / HW;
            const int hw  = m - n * HW;
            const int h   = hw / W_IMG;
            const int wp  = hw - h * W_IMG;
            const int p   = (h >> 3) * NWIN + (wp >> 3);
            const int pix = ((h & 7) << 3) + (wp & 7);
            const size_t npix = (size_t)((n * P2 + p) * W2 + pix);
            uint32_t* dsth = isq ? ((uint32_t*)g_qh  + npix * 256 + (o0 >> 1))
                                 : ((uint32_t*)g_kvh + npix * 512 + ((o0 - QKC) >> 1));
#pragma unroll
            for (int nt = 0; nt < 8; nt++) {
                const int col = nw + nt * 8 + lq * 2;
                float vx = c[mt][nt][half * 2 + 0] + bqkv[o0 + col];
                float vy = c[mt][nt][half * 2 + 1] + bqkv[o0 + col + 1];
                dsth[col >> 1] = isq ? pack2(vx * SCALE, vy * SCALE) : pack2(vx, vy);
            }
        }
    }
#undef K1_ISSUE
}

// ===========================================================================
// Kernel 2: window means from fp16 q/kv, fp32 accumulation.
// ===========================================================================
__global__ __launch_bounds__(256) void k2_mean() {
    const int np = blockIdx.x;
    const int c2 = threadIdx.x;
    const uint32_t* qb = (const uint32_t*)g_qh  + (size_t)np * W2 * 256 + c2;
    const uint32_t* kb = (const uint32_t*)g_kvh + (size_t)np * W2 * 512 + c2;
    float sqx = 0.f, sqy = 0.f, skx = 0.f, sky = 0.f;
#pragma unroll 8
    for (int pix = 0; pix < W2; pix++) {
        uint32_t qv = qb[(size_t)pix * 256];
        uint32_t kv = kb[(size_t)pix * 512];
        float2 qf = __half22float2(*reinterpret_cast<__half2*>(&qv));
        float2 kf = __half22float2(*reinterpret_cast<__half2*>(&kv));
        sqx += qf.x; sqy += qf.y;
        skx += kf.x; sky += kf.y;
    }
    *(float2*)(g_qwin + (size_t)np * 512 + 2 * c2) = make_float2(sqx * (1.f/64.f), sqy * (1.f/64.f));
    *(float2*)(g_kwin + (size_t)np * 512 + 2 * c2) = make_float2(skx * (1.f/64.f), sky * (1.f/64.f));
}

// ===========================================================================
// Kernel 3: routing logits + top-4 (warp-parallel argmax). grid 784 x 128.
// ===========================================================================
__global__ __launch_bounds__(128) void k3_route() {
    __shared__ float qs[512];
    __shared__ float lg[P2];
    const int np = blockIdx.x;
    const int n  = np / P2;
    const int t  = threadIdx.x;
    for (int c = t; c < 512; c += 128)
        qs[c] = g_qwin[(size_t)np * 512 + c];
    __syncthreads();
    {
        const int win = (t >> 1) < P2 ? (t >> 1) : (P2 - 1);
        const int hf  = t & 1;
        const float4* kr = (const float4*)(g_kwin + (size_t)(n * P2 + win) * 512) + hf * 64;
        const float*  qh = qs + hf * 256;
        float s = 0.f;
#pragma unroll 8
        for (int c4 = 0; c4 < 64; c4++) {
            float4 k4 = kr[c4];
            s += qh[c4 * 4 + 0] * k4.x + qh[c4 * 4 + 1] * k4.y +
                 qh[c4 * 4 + 2] * k4.z + qh[c4 * 4 + 3] * k4.w;
        }
        s += __shfl_xor_sync(0xffffffffu, s, 1);
        if (hf == 0 && (t >> 1) < P2) lg[win] = s;
    }
    __syncthreads();
    if (t < 32) {
        float v0 = (t < P2)      ? lg[t]      : -1e30f;
        float v1 = (t + 32 < P2) ? lg[t + 32] : -1e30f;
#pragma unroll
        for (int sel = 0; sel < TOPK; sel++) {
            float m; int idx;
            if (v0 >= v1) { m = v0; idx = t; } else { m = v1; idx = t + 32; }
#pragma unroll
            for (int off = 16; off; off >>= 1) {
                float om = __shfl_xor_sync(0xffffffffu, m, off);
                int   oi = __shfl_xor_sync(0xffffffffu, idx, off);
                if (om > m || (om == m && oi < idx)) { m = om; idx = oi; }
            }
            if (t == 0) g_idx[np * TOPK + sel] = idx;
            const int wsel = __shfl_sync(0xffffffffu, idx, 0);
            if (wsel == t)      v0 = -1e30f;
            if (wsel == t + 32) v1 = -1e30f;
        }
    }
}

// ===========================================================================
// Kernel 4: attention, fp16 mma + double-buffered cp.async KV (unchanged).
// ===========================================================================
#define K4_TILE 9216                   // 64 * 144
#define K4_SMEM (5 * K4_TILE)

__global__ __launch_bounds__(128) void k4_attn_tc() {
    extern __shared__ char smc[];
    const uint32_t sb = smem_u32(smc);
    const uint32_t Qb = sb;

    const int head = blockIdx.x;
    const int np   = blockIdx.y;
    const int n    = np / P2;
    const int t    = threadIdx.x;
    const int wid  = t >> 5;
    const int lane = t & 31;
    const int mw   = wid * 16;
    const int lr   = lane >> 2;
    const int lq   = lane & 3;
    const int grp  = lane >> 3, li = lane & 7;

    const int q_r   = mw + li + ((grp & 1) ? 8 : 0);
    const int q_k   = (grp & 2) ? 8 : 0;
    const int k_n   = li + ((grp & 2) ? 8 : 0);
    const int k_k   = (grp & 1) ? 8 : 0;
    const int v_key = li + ((grp & 1) ? 8 : 0);
    const int v_d   = (grp & 2) ? 8 : 0;

    int widx[TOPK];
#pragma unroll
    for (int i = 0; i < TOPK; i++) widx[i] = g_idx[np * TOPK + i];

#define K4_KV_ISSUE(ts_) do {                                                   \
    const int s_ = (ts_) & 1;                                                   \
    const uint32_t Kb_ = sb + (1 + 2 * s_) * K4_TILE;                           \
    const uint32_t Vb_ = Kb_ + K4_TILE;                                         \
    const __half* kvsrc_ = g_kvh + (size_t)(n * P2 + widx[ts_]) * 64 * 1024 + head * HD; \
    _Pragma("unroll")                                                           \
    for (int i_ = 0; i_ < 4; i_++) {                                            \
        int cq_ = i_ * 128 + t;                                                 \
        int pix_ = cq_ >> 3, h8_ = (cq_ & 7) * 8;                               \
        CP_ASYNC16(Kb_ + pix_ * 144 + h8_ * 2, kvsrc_ + (size_t)pix_ * 1024 + h8_);       \
        CP_ASYNC16(Vb_ + pix_ * 144 + h8_ * 2, kvsrc_ + (size_t)pix_ * 1024 + 512 + h8_); \
    }                                                                           \
} while (0)

    {
        const __half* qsrc = g_qh + (size_t)np * 64 * 512 + head * HD;
#pragma unroll
        for (int i = 0; i < 4; i++) {
            int cq = i * 128 + t;
            int pix = cq >> 3, h8 = (cq & 7) * 8;
            CP_ASYNC16(Qb + pix * 144 + h8 * 2, qsrc + (size_t)pix * 512 + h8);
        }
        K4_KV_ISSUE(0);
        CP_COMMIT();
        K4_KV_ISSUE(1);
        CP_COMMIT();
    }

    float Of[8][4];
#pragma unroll
    for (int dt = 0; dt < 8; dt++)
#pragma unroll
        for (int i = 0; i < 4; i++) Of[dt][i] = 0.f;
    float mrun0 = -1e30f, mrun1 = -1e30f, lrun0 = 0.f, lrun1 = 0.f;

    for (int tsel = 0; tsel < TOPK; tsel++) {
        CP_WAIT(1);
        __syncthreads();
        const uint32_t Kb = sb + (1 + 2 * (tsel & 1)) * K4_TILE;
        const uint32_t Vb = Kb + K4_TILE;

        float sf[8][4];
#pragma unroll
        for (int nt = 0; nt < 8; nt++)
#pragma unroll
            for (int i = 0; i < 4; i++) sf[nt][i] = 0.f;
#pragma unroll
        for (int ks = 0; ks < 4; ks++) {
            uint32_t a[4];
            LDSM_X4(a, Qb + q_r * 144 + (ks * 16 + q_k) * 2);
#pragma unroll
            for (int ntp = 0; ntp < 4; ntp++) {
                uint32_t b[4];
                LDSM_X4(b, Kb + (ntp * 16 + k_n) * 144 + (ks * 16 + k_k) * 2);
                mma_f16(sf[2 * ntp],     a, b[0], b[1]);
                mma_f16(sf[2 * ntp + 1], a, b[2], b[3]);
            }
        }

        float mx0 = -1e30f, mx1 = -1e30f;
#pragma unroll
        for (int nt = 0; nt < 8; nt++) {
            mx0 = fmaxf(mx0, fmaxf(sf[nt][0], sf[nt][1]));
            mx1 = fmaxf(mx1, fmaxf(sf[nt][2], sf[nt][3]));
        }
        mx0 = fmaxf(mx0, __shfl_xor_sync(0xffffffffu, mx0, 1));
        mx0 = fmaxf(mx0, __shfl_xor_sync(0xffffffffu, mx0, 2));
        mx1 = fmaxf(mx1, __shfl_xor_sync(0xffffffffu, mx1, 1));
        mx1 = fmaxf(mx1, __shfl_xor_sync(0xffffffffu, mx1, 2));
        const float mn0 = fmaxf(mrun0, mx0);
        const float mn1 = fmaxf(mrun1, mx1);
        const float cor0 = __expf(mrun0 - mn0);
        const float cor1 = __expf(mrun1 - mn1);
        float ls0 = 0.f, ls1 = 0.f;
        uint32_t pf0[8], pf1[8];
#pragma unroll
        for (int nt = 0; nt < 8; nt++) {
            __half2 h0 = __floats2half2_rn(__expf(sf[nt][0] - mn0), __expf(sf[nt][1] - mn0));
            __half2 h1 = __floats2half2_rn(__expf(sf[nt][2] - mn1), __expf(sf[nt][3] - mn1));
            float2 f0 = __half22float2(h0);
            float2 f1 = __half22float2(h1);
            ls0 += f0.x + f0.y;
            ls1 += f1.x + f1.y;
            pf0[nt] = *reinterpret_cast<uint32_t*>(&h0);
            pf1[nt] = *reinterpret_cast<uint32_t*>(&h1);
        }
        ls0 += __shfl_xor_sync(0xffffffffu, ls0, 1);
        ls0 += __shfl_xor_sync(0xffffffffu, ls0, 2);
        ls1 += __shfl_xor_sync(0xffffffffu, ls1, 1);
        ls1 += __shfl_xor_sync(0xffffffffu, ls1, 2);
        lrun0 = lrun0 * cor0 + ls0;
        lrun1 = lrun1 * cor1 + ls1;
        mrun0 = mn0; mrun1 = mn1;
#pragma unroll
        for (int dt = 0; dt < 8; dt++) {
            Of[dt][0] *= cor0; Of[dt][1] *= cor0;
            Of[dt][2] *= cor1; Of[dt][3] *= cor1;
        }

#pragma unroll
        for (int ks = 0; ks < 4; ks++) {
            uint32_t a[4] = {pf0[2 * ks], pf1[2 * ks], pf0[2 * ks + 1], pf1[2 * ks + 1]};
#pragma unroll
            for (int dtp = 0; dtp < 4; dtp++) {
                uint32_t b[4];
                LDSM_X4T(b, Vb + (ks * 16 + v_key) * 144 + (dtp * 16 + v_d) * 2);
                mma_f16(Of[2 * dtp],     a, b[0], b[1]);
                mma_f16(Of[2 * dtp + 1], a, b[2], b[3]);
            }
        }

        __syncthreads();
        if (tsel + 2 < TOPK) { K4_KV_ISSUE(tsel + 2); }
        CP_COMMIT();
    }

    const float inv0 = 1.f / lrun0;
    const float inv1 = 1.f / lrun1;
    uint32_t* d0 = (uint32_t*)g_aoh + ((size_t)np * W2 + mw + lr)     * 256 + head * 32;
    uint32_t* d1 = (uint32_t*)g_aoh + ((size_t)np * W2 + mw + lr + 8) * 256 + head * 32;
#pragma unroll
    for (int dt = 0; dt < 8; dt++) {
        d0[dt * 4 + lq] = pack2(Of[dt][0] * inv0, Of[dt][1] * inv0);
        d1[dt * 4 + lq] = pack2(Of[dt][2] * inv1, Of[dt][3] * inv1);
    }
#undef K4_KV_ISSUE
}

// ===========================================================================
// Kernel 5: LePE depthwise 3x3 + attn out, half2 channels, NCHW fp32 output.
// grid (8 cblk of 64ch, 49 p, 16 n), block 256 = 32 half2-ch x 8 rows.
// ===========================================================================
__global__ __launch_bounds__(256) void k5_out(const float* __restrict__ wlepe,
                                              const float* __restrict__ blepe,
                                              float* __restrict__ out) {
    __shared__ float2 stage[64][33];   // [pix][c2]
    const int cb = blockIdx.x;
    const int p  = blockIdx.y;
    const int n  = blockIdx.z;
    const int c0 = cb * 64;
    const int t  = threadIdx.x;
    const int c2 = t & 31;             // half2 channel pair
    const int pr = t >> 5;             // 0..7

    const int ce = c0 + 2 * c2;
    float wl0[9], wl1[9];
#pragma unroll
    for (int k = 0; k < 9; k++) {
        wl0[k] = wlepe[ce * 9 + k];
        wl1[k] = wlepe[(ce + 1) * 9 + k];
    }
    const float bias0 = blepe[ce];
    const float bias1 = blepe[ce + 1];

    const int wh0 = (p / NWIN) * 8;
    const int ww0 = (p % NWIN) * 8;

    for (int pg = 0; pg < 8; pg++) {
        int pix = pg * 8 + pr;
        int ih = pix >> 3, iw = pix & 7;
        int h = wh0 + ih, w = ww0 + iw;
        float a0 = bias0, a1 = bias1;
#pragma unroll
        for (int kh = 0; kh < 3; kh++) {
            int hh = h + kh - 1;
            if (hh < 0 || hh >= H_IMG) continue;
#pragma unroll
            for (int kw = 0; kw < 3; kw++) {
                int ww = w + kw - 1;
                if (ww < 0 || ww >= W_IMG) continue;
                int pp   = (hh >> 3) * NWIN + (ww >> 3);
                int ppix = ((hh & 7) << 3) + (ww & 7);
                uint32_t vv = *(const uint32_t*)&g_kvh[
                    ((size_t)(n * P2 + pp) * W2 + ppix) * 1024 + 512 + ce];
                float2 vf = __half22float2(*reinterpret_cast<__half2*>(&vv));
                a0 += vf.x * wl0[kh * 3 + kw];
                a1 += vf.y * wl1[kh * 3 + kw];
            }
        }
        uint32_t av = *(const uint32_t*)&g_aoh[((size_t)(n * P2 + p) * W2 + pix) * 512 + ce];
        float2 af = __half22float2(*reinterpret_cast<__half2*>(&av));
        stage[pix][c2] = make_float2(a0 + af.x, a1 + af.y);
    }
    __syncthreads();

    // write: 64 channels x 64 pixels; thread: wc = t>>2 (channel), (t&3)*2 = wx
    const int wc = t >> 2;             // 0..63
    const int wx = (t & 3) * 2;        // 0,2,4,6
    const int cpair = wc >> 1;
    const int csel  = wc & 1;
    const size_t obase = ((size_t)n * C_DIM + c0 + wc) * HW;
    for (int h = 0; h < 8; h++) {
        float2 s0 = stage[h * 8 + wx][cpair];
        float2 s1 = stage[h * 8 + wx + 1][cpair];
        float2 v = csel ? make_float2(s0.y, s1.y) : make_float2(s0.x, s1.x);
        *(float2*)(out + obase + (size_t)(wh0 + h) * W_IMG + ww0 + wx) = v;
    }
}

// ===========================================================================
extern "C" void kernel_launch(void* const* d_in, const int* in_sizes, int n_in,
                              void* d_out, int out_size) {
    const float* x      = (const float*)d_in[0];
    const float* w_qkv  = (const float*)d_in[1];
    const float* b_qkv  = (const float*)d_in[2];
    const float* w_lepe = (const float*)d_in[3];
    const float* b_lepe = (const float*)d_in[4];
    float* out = (float*)d_out;

    cudaFuncSetAttribute(k1_qkv_tc, cudaFuncAttributeMaxDynamicSharedMemorySize, K1_SMEM);
    cudaFuncSetAttribute(k4_attn_tc, cudaFuncAttributeMaxDynamicSharedMemorySize, K4_SMEM);

    kd_nop<<<1, 32>>>();
    kd_nop<<<1, 32>>>();
    k0_half<<<25088, 256>>>(x, w_qkv);
    k1_qkv_tc<<<dim3(12, 392), 256, K1_SMEM>>>(b_qkv);
    k2_mean<<<784, 256>>>();
    k3_route<<<784, 128>>>();
    k4_attn_tc<<<dim3(HEADS, N_IMG * P2), 128, K4_SMEM>>>();
    k5_out<<<dim3(8, P2, N_IMG), 256>>>(w_lepe, b_lepe, out);
}